// round 4
// baseline (speedup 1.0000x reference)
#include <cuda_runtime.h>
#include <math.h>

// ---------------- problem constants ----------------
#define EDG   262144
#define BGR   8
#define NNODE 512
#define NDIM  128
#define EDIM  64
#define GDIM  32
#define FIN   320
#define XDIM  352
#define H1D   256
#define AHD   64
#define NOUT1 320
#define OUTD  64
#define NH    4
#define NSEG  (BGR*NNODE)

// ---------------- device scratch ----------------
__device__ float g_x[(size_t)EDG * XDIM];
__device__ float g_h[(size_t)EDG * NOUT1];
__device__ float g_Wcat[XDIM * NOUT1];
__device__ float g_bcat[NOUT1];
__device__ float g_ae[EDG * NH];
__device__ float g_den[NSEG * NH];
__device__ float g_invden[NSEG * NH];

// ---------------- prep ----------------
__global__ void prep_kernel(const float* __restrict__ W1, const float* __restrict__ b1,
                            const float* __restrict__ A1, const float* __restrict__ ab1,
                            float* __restrict__ pooled)
{
    int i = blockIdx.x * blockDim.x + threadIdx.x;
    if (i < XDIM * NOUT1) {
        int k = i / NOUT1, n = i % NOUT1;
        g_Wcat[i] = (n < H1D) ? W1[k * H1D + n] : A1[k * AHD + (n - H1D)];
    }
    if (i < NOUT1) g_bcat[i] = (i < H1D) ? b1[i] : ab1[i - H1D];
    if (i < NSEG * NH) g_den[i] = 0.f;
    if (i < NSEG * OUTD) pooled[i] = 0.f;
}

// ---------------- K1: gather + LayerNorm + ctxt ----------------
__global__ void build_x_kernel(const float* __restrict__ nodes,
                               const float* __restrict__ edges0,
                               const float* __restrict__ globs,
                               const float* __restrict__ ln_g,
                               const float* __restrict__ ln_b,
                               const int* __restrict__ bidx,
                               const int* __restrict__ sidx,
                               const int* __restrict__ ridx)
{
    int e = blockIdx.x * (blockDim.x >> 5) + (threadIdx.x >> 5);
    int lane = threadIdx.x & 31;
    if (e >= EDG) return;
    int b = bidx[e], s = sidx[e], r = ridx[e];
    const float* srow = nodes + ((size_t)b * NNODE + s) * NDIM;
    const float* rrow = nodes + ((size_t)b * NNODE + r) * NDIM;
    const float* erow = edges0 + (size_t)e * EDIM;

    float v[10];
    v[0] = erow[lane];
    v[1] = erow[lane + 32];
#pragma unroll
    for (int i = 0; i < 4; i++) v[2 + i] = srow[lane + 32 * i];
#pragma unroll
    for (int i = 0; i < 4; i++) v[6 + i] = rrow[lane + 32 * i];

    float s1 = 0.f, s2 = 0.f;
#pragma unroll
    for (int i = 0; i < 10; i++) { s1 += v[i]; s2 += v[i] * v[i]; }
#pragma unroll
    for (int off = 16; off > 0; off >>= 1) {
        s1 += __shfl_xor_sync(0xffffffffu, s1, off);
        s2 += __shfl_xor_sync(0xffffffffu, s2, off);
    }
    float mu   = s1 * (1.f / FIN);
    float var  = s2 * (1.f / FIN) - mu * mu;
    float rstd = rsqrtf(var + 1e-5f);

    float* xr = g_x + (size_t)e * XDIM;
#pragma unroll
    for (int i = 0; i < 10; i++) {
        int idx;
        if (i < 2)      idx = lane + 32 * i;
        else if (i < 6) idx = 64  + lane + 32 * (i - 2);
        else            idx = 192 + lane + 32 * (i - 6);
        xr[idx] = (v[i] - mu) * rstd * ln_g[idx] + ln_b[idx];
    }
    xr[FIN + lane] = globs[b * GDIM + lane];
}

// ---------------- GEMM1: g_h = silu(g_x @ [W1|A1] + [b1|ab1]) ----------------
__global__ void __launch_bounds__(256) gemm1_kernel()
{
    constexpr int KK = XDIM, LDA = XDIM, NTOT = NOUT1;
    constexpr int BM = 64, BK = 16;
    __shared__ float As[BK][BM + 4];
    __shared__ float Bs[BK][64];

    const int t  = threadIdx.x;
    const int m0 = blockIdx.y * BM;
    const int n0 = blockIdx.x * 64;
    const int tm = t >> 4, tn = t & 15;
    const int ak = t & 15, am = t >> 4;
    const int bk = t >> 4, bn = (t & 15) * 4;

    float acc[4][4];
#pragma unroll
    for (int i = 0; i < 4; i++)
#pragma unroll
        for (int j = 0; j < 4; j++) acc[i][j] = 0.f;

    const float* Aptr = g_x + (size_t)m0 * LDA;

#pragma unroll 1
    for (int k0 = 0; k0 < KK; k0 += BK) {
        float av[4];
#pragma unroll
        for (int p = 0; p < 4; p++)
            av[p] = Aptr[(size_t)(am + 16 * p) * LDA + (k0 + ak)];
        float4 wv = *reinterpret_cast<const float4*>(&g_Wcat[(size_t)(k0 + bk) * NTOT + n0 + bn]);

        __syncthreads();
#pragma unroll
        for (int p = 0; p < 4; p++) As[ak][am + 16 * p] = av[p];
        *reinterpret_cast<float4*>(&Bs[bk][bn]) = wv;
        __syncthreads();

#pragma unroll
        for (int kk = 0; kk < BK; kk++) {
            float4 a4 = *reinterpret_cast<const float4*>(&As[kk][tm * 4]);
            float4 b4 = *reinterpret_cast<const float4*>(&Bs[kk][tn * 4]);
            float a[4] = {a4.x, a4.y, a4.z, a4.w};
            float b[4] = {b4.x, b4.y, b4.z, b4.w};
#pragma unroll
            for (int i = 0; i < 4; i++)
#pragma unroll
                for (int j = 0; j < 4; j++)
                    acc[i][j] = fmaf(a[i], b[j], acc[i][j]);
        }
    }

    float4 bias4 = *reinterpret_cast<const float4*>(&g_bcat[n0 + tn * 4]);
    float bv[4] = {bias4.x, bias4.y, bias4.z, bias4.w};
#pragma unroll
    for (int i = 0; i < 4; i++) {
        int m = m0 + tm * 4 + i;
        float ov[4];
#pragma unroll
        for (int j = 0; j < 4; j++) {
            float v = acc[i][j] + bv[j];
            ov[j] = v / (1.f + __expf(-v));
        }
        *reinterpret_cast<float4*>(&g_h[(size_t)m * NTOT + n0 + tn * 4]) =
            make_float4(ov[0], ov[1], ov[2], ov[3]);
    }
}

// ---------------- GEMM2: newe = g_h[:, :256] @ W2 + b2 + edges0 ----------------
__global__ void __launch_bounds__(256) gemm2_kernel(const float* __restrict__ W2,
                                                    const float* __restrict__ b2,
                                                    const float* __restrict__ edges0,
                                                    float* __restrict__ Cout)
{
    constexpr int KK = H1D, LDA = NOUT1, NTOT = OUTD;
    constexpr int BM = 64, BK = 16;
    __shared__ float As[BK][BM + 4];
    __shared__ float Bs[BK][64];

    const int t  = threadIdx.x;
    const int m0 = blockIdx.y * BM;
    const int tm = t >> 4, tn = t & 15;
    const int ak = t & 15, am = t >> 4;
    const int bk = t >> 4, bn = (t & 15) * 4;

    float acc[4][4];
#pragma unroll
    for (int i = 0; i < 4; i++)
#pragma unroll
        for (int j = 0; j < 4; j++) acc[i][j] = 0.f;

    const float* Aptr = g_h + (size_t)m0 * LDA;

#pragma unroll 1
    for (int k0 = 0; k0 < KK; k0 += BK) {
        float av[4];
#pragma unroll
        for (int p = 0; p < 4; p++)
            av[p] = Aptr[(size_t)(am + 16 * p) * LDA + (k0 + ak)];
        float4 wv = *reinterpret_cast<const float4*>(&W2[(size_t)(k0 + bk) * NTOT + bn]);

        __syncthreads();
#pragma unroll
        for (int p = 0; p < 4; p++) As[ak][am + 16 * p] = av[p];
        *reinterpret_cast<float4*>(&Bs[bk][bn]) = wv;
        __syncthreads();

#pragma unroll
        for (int kk = 0; kk < BK; kk++) {
            float4 a4 = *reinterpret_cast<const float4*>(&As[kk][tm * 4]);
            float4 b4 = *reinterpret_cast<const float4*>(&Bs[kk][tn * 4]);
            float a[4] = {a4.x, a4.y, a4.z, a4.w};
            float b[4] = {b4.x, b4.y, b4.z, b4.w};
#pragma unroll
            for (int i = 0; i < 4; i++)
#pragma unroll
                for (int j = 0; j < 4; j++)
                    acc[i][j] = fmaf(a[i], b[j], acc[i][j]);
        }
    }

    float4 bias4 = *reinterpret_cast<const float4*>(&b2[tn * 4]);
    float bv[4] = {bias4.x, bias4.y, bias4.z, bias4.w};
#pragma unroll
    for (int i = 0; i < 4; i++) {
        int m = m0 + tm * 4 + i;
        float4 r4 = *reinterpret_cast<const float4*>(&edges0[(size_t)m * NTOT + tn * 4]);
        *reinterpret_cast<float4*>(&Cout[(size_t)m * NTOT + tn * 4]) =
            make_float4(acc[i][0] + bv[0] + r4.x, acc[i][1] + bv[1] + r4.y,
                        acc[i][2] + bv[2] + r4.z, acc[i][3] + bv[3] + r4.w);
    }
}

// ---------------- K4: attention logits, exp, denom ----------------
__global__ void attn_logits_kernel(const float* __restrict__ A2, const float* __restrict__ ab2,
                                   const int* __restrict__ bidx, const int* __restrict__ ridx)
{
    __shared__ float sA2[AHD * NH];
    int t = threadIdx.x;
    if (t < AHD * NH) sA2[t] = A2[t];
    __syncthreads();

    int e = blockIdx.x * blockDim.x + t;
    if (e >= EDG) return;
    const float* hr = g_h + (size_t)e * NOUT1 + H1D;

    float acc[NH] = {ab2[0], ab2[1], ab2[2], ab2[3]};
#pragma unroll
    for (int q = 0; q < AHD / 4; q++) {
        float4 v4 = *reinterpret_cast<const float4*>(&hr[q * 4]);
        float v[4] = {v4.x, v4.y, v4.z, v4.w};
#pragma unroll
        for (int u = 0; u < 4; u++) {
            int j = q * 4 + u;
#pragma unroll
            for (int h = 0; h < NH; h++)
                acc[h] = fmaf(v[u], sA2[j * NH + h], acc[h]);
        }
    }
    int seg = bidx[e] * NNODE + ridx[e];
#pragma unroll
    for (int h = 0; h < NH; h++) {
        float ae = __expf(acc[h] * 0.125f);
        g_ae[e * NH + h] = ae;
        atomicAdd(&g_den[seg * NH + h], ae);
    }
}

__global__ void invden_kernel()
{
    int i = blockIdx.x * blockDim.x + threadIdx.x;
    if (i < NSEG * NH) {
        float d = g_den[i];
        g_invden[i] = (d > 0.f) ? (1.f / d) : 0.f;
    }
}

// ---------------- K5: pooled scatter ----------------
__global__ void pool_kernel(const int* __restrict__ bidx, const int* __restrict__ ridx,
                            const float* __restrict__ newe, float* __restrict__ pooled)
{
    int gid = blockIdx.x * blockDim.x + threadIdx.x;
    int e = gid >> 6;
    int c = gid & 63;
    int seg = bidx[e] * NNODE + ridx[e];
    int h = c >> 4;
    float attn = g_ae[e * NH + h] * g_invden[seg * NH + h];
    atomicAdd(&pooled[seg * OUTD + c], newe[gid] * attn);
}

// ---------------- entry ----------------
extern "C" void kernel_launch(void* const* d_in, const int* in_sizes, int n_in,
                              void* d_out, int out_size)
{
    const float* nodes  = (const float*)d_in[0];
    const float* edges0 = (const float*)d_in[1];
    const float* globs  = (const float*)d_in[2];
    const float* ln_g   = (const float*)d_in[3];
    const float* ln_b   = (const float*)d_in[4];
    const float* W1     = (const float*)d_in[5];
    const float* b1     = (const float*)d_in[6];
    const float* W2     = (const float*)d_in[7];
    const float* b2     = (const float*)d_in[8];
    const float* A1     = (const float*)d_in[9];
    const float* ab1    = (const float*)d_in[10];
    const float* A2     = (const float*)d_in[11];
    const float* ab2    = (const float*)d_in[12];
    const int*   bidx   = (const int*)d_in[13];
    const int*   sidx   = (const int*)d_in[14];
    const int*   ridx   = (const int*)d_in[15];

    float* out    = (float*)d_out;
    float* newe   = out;
    float* pooled = out + (size_t)EDG * OUTD;

    prep_kernel<<<(NSEG * OUTD + 255) / 256, 256>>>(W1, b1, A1, ab1, pooled);
    build_x_kernel<<<EDG / 8, 256>>>(nodes, edges0, globs, ln_g, ln_b, bidx, sidx, ridx);
    gemm1_kernel<<<dim3(NOUT1 / 64, EDG / 64), 256>>>();
    gemm2_kernel<<<dim3(1, EDG / 64), 256>>>(W2, b2, edges0, newe);
    attn_logits_kernel<<<EDG / 256, 256>>>(A2, ab2, bidx, ridx);
    invden_kernel<<<(NSEG * NH + 255) / 256, 256>>>();
    pool_kernel<<<(EDG * OUTD) / 256, 256>>>(bidx, ridx, newe, pooled);
}

// round 7
// speedup vs baseline: 2.2976x; 2.2976x over previous
#include <cuda_runtime.h>
#include <math.h>
#include <stdint.h>

// ---------------- problem constants ----------------
#define EDG   262144
#define BGR   8
#define NNODE 512
#define NDIM  128
#define EDIM  64
#define GDIM  32
#define FIN   320
#define XDIM  352
#define H1D   256
#define AHD   64
#define NOUT1 320
#define OUTD  64
#define NH    4
#define NSEG  (BGR*NNODE)

// ---------------- device scratch ----------------
__device__ float g_x[(size_t)EDG * XDIM];
__device__ float g_h[(size_t)EDG * NOUT1];
__device__ float g_Wcat[XDIM * NOUT1];
__device__ float g_bcat[NOUT1];
__device__ float g_ae[EDG * NH];
__device__ float g_den[NSEG * NH];
__device__ float g_invden[NSEG * NH];

// ---------------- helpers ----------------
__device__ __forceinline__ uint32_t f2tf(float f) {
    uint32_t r;
    asm("cvt.rna.tf32.f32 %0, %1;" : "=r"(r) : "f"(f));
    return r;
}

__device__ __forceinline__ void mma_tf32(float c[4],
                                         uint32_t a0, uint32_t a1, uint32_t a2, uint32_t a3,
                                         uint32_t b0, uint32_t b1)
{
    asm volatile(
        "mma.sync.aligned.m16n8k8.row.col.f32.tf32.tf32.f32 "
        "{%0,%1,%2,%3}, {%4,%5,%6,%7}, {%8,%9}, {%0,%1,%2,%3};"
        : "+f"(c[0]), "+f"(c[1]), "+f"(c[2]), "+f"(c[3])
        : "r"(a0), "r"(a1), "r"(a2), "r"(a3), "r"(b0), "r"(b1));
}

__device__ __forceinline__ float silu_f(float v) { return v / (1.f + __expf(-v)); }

// ---------------- prep ----------------
__global__ void prep_kernel(const float* __restrict__ W1, const float* __restrict__ b1,
                            const float* __restrict__ A1, const float* __restrict__ ab1,
                            float* __restrict__ pooled)
{
    int i = blockIdx.x * blockDim.x + threadIdx.x;
    if (i < XDIM * NOUT1) {
        int k = i / NOUT1, n = i % NOUT1;
        g_Wcat[i] = (n < H1D) ? W1[k * H1D + n] : A1[k * AHD + (n - H1D)];
    }
    if (i < NOUT1) g_bcat[i] = (i < H1D) ? b1[i] : ab1[i - H1D];
    if (i < NSEG * NH) g_den[i] = 0.f;
    if (i < NSEG * OUTD) pooled[i] = 0.f;
}

// ---------------- K1: gather + LayerNorm + ctxt ----------------
__global__ void build_x_kernel(const float* __restrict__ nodes,
                               const float* __restrict__ edges0,
                               const float* __restrict__ globs,
                               const float* __restrict__ ln_g,
                               const float* __restrict__ ln_b,
                               const int* __restrict__ bidx,
                               const int* __restrict__ sidx,
                               const int* __restrict__ ridx)
{
    int e = blockIdx.x * (blockDim.x >> 5) + (threadIdx.x >> 5);
    int lane = threadIdx.x & 31;
    if (e >= EDG) return;
    int b = bidx[e], s = sidx[e], r = ridx[e];
    const float* srow = nodes + ((size_t)b * NNODE + s) * NDIM;
    const float* rrow = nodes + ((size_t)b * NNODE + r) * NDIM;
    const float* erow = edges0 + (size_t)e * EDIM;

    float v[10];
    v[0] = erow[lane];
    v[1] = erow[lane + 32];
#pragma unroll
    for (int i = 0; i < 4; i++) v[2 + i] = srow[lane + 32 * i];
#pragma unroll
    for (int i = 0; i < 4; i++) v[6 + i] = rrow[lane + 32 * i];

    float s1 = 0.f, s2 = 0.f;
#pragma unroll
    for (int i = 0; i < 10; i++) { s1 += v[i]; s2 += v[i] * v[i]; }
#pragma unroll
    for (int off = 16; off > 0; off >>= 1) {
        s1 += __shfl_xor_sync(0xffffffffu, s1, off);
        s2 += __shfl_xor_sync(0xffffffffu, s2, off);
    }
    float mu   = s1 * (1.f / FIN);
    float var  = s2 * (1.f / FIN) - mu * mu;
    float rstd = rsqrtf(var + 1e-5f);

    float* xr = g_x + (size_t)e * XDIM;
#pragma unroll
    for (int i = 0; i < 10; i++) {
        int idx;
        if (i < 2)      idx = lane + 32 * i;
        else if (i < 6) idx = 64  + lane + 32 * (i - 2);
        else            idx = 192 + lane + 32 * (i - 6);
        xr[idx] = (v[i] - mu) * rstd * ln_g[idx] + ln_b[idx];
    }
    xr[FIN + lane] = globs[b * GDIM + lane];
}

// ================= tf32 tensor-core GEMM1 =================
// g_h[E,320] = silu(g_x[E,352] @ g_Wcat[352,320] + g_bcat)
// BM=128, BN=64, BK=32, 256 threads, warps 4(M)x2(N), warp tile 32x32.
__global__ void __launch_bounds__(256) gemm1_tc()
{
    constexpr int LDA = XDIM, KK = XDIM, NTOT = NOUT1;
    constexpr int SA = 36, SB = 72;
    __shared__ uint32_t As[128 * SA];   // [m][k] tf32 bits, padded
    __shared__ uint32_t Bs[32 * SB];    // [k][n] tf32 bits, padded

    const int t = threadIdx.x, lane = t & 31, wid = t >> 5;
    const int g4 = lane >> 2, t4 = lane & 3;
    const int wm = (wid & 3) * 32, wn = (wid >> 2) * 32;
    const int m0 = blockIdx.y * 128, n0 = blockIdx.x * 64;

    float c[2][4][4];
#pragma unroll
    for (int mi = 0; mi < 2; mi++)
#pragma unroll
        for (int ni = 0; ni < 4; ni++)
#pragma unroll
            for (int q = 0; q < 4; q++) c[mi][ni][q] = 0.f;

    const float* Ap = g_x + (size_t)m0 * LDA;

    // staging index precompute
    int arow[4], ac4[4];
#pragma unroll
    for (int i = 0; i < 4; i++) { int idx = t + 256 * i; arow[i] = idx >> 3; ac4[i] = idx & 7; }
    int brow[2], bc4[2];
#pragma unroll
    for (int i = 0; i < 2; i++) { int idx = t + 256 * i; brow[i] = idx >> 4; bc4[i] = idx & 15; }

    float4 areg[4], breg[2];
#pragma unroll
    for (int i = 0; i < 4; i++)
        areg[i] = *reinterpret_cast<const float4*>(&Ap[(size_t)arow[i] * LDA + ac4[i] * 4]);
#pragma unroll
    for (int i = 0; i < 2; i++)
        breg[i] = *reinterpret_cast<const float4*>(&g_Wcat[(size_t)brow[i] * NTOT + n0 + bc4[i] * 4]);

#pragma unroll 1
    for (int k0 = 0; k0 < KK; k0 += 32) {
        __syncthreads();
#pragma unroll
        for (int i = 0; i < 4; i++) {
            uint4 u = make_uint4(f2tf(areg[i].x), f2tf(areg[i].y), f2tf(areg[i].z), f2tf(areg[i].w));
            *reinterpret_cast<uint4*>(&As[arow[i] * SA + ac4[i] * 4]) = u;
        }
#pragma unroll
        for (int i = 0; i < 2; i++) {
            uint4 u = make_uint4(f2tf(breg[i].x), f2tf(breg[i].y), f2tf(breg[i].z), f2tf(breg[i].w));
            *reinterpret_cast<uint4*>(&Bs[brow[i] * SB + bc4[i] * 4]) = u;
        }
        __syncthreads();

        if (k0 + 32 < KK) {
#pragma unroll
            for (int i = 0; i < 4; i++)
                areg[i] = *reinterpret_cast<const float4*>(&Ap[(size_t)arow[i] * LDA + k0 + 32 + ac4[i] * 4]);
#pragma unroll
            for (int i = 0; i < 2; i++)
                breg[i] = *reinterpret_cast<const float4*>(&g_Wcat[(size_t)(k0 + 32 + brow[i]) * NTOT + n0 + bc4[i] * 4]);
        }

#pragma unroll
        for (int ks = 0; ks < 4; ks++) {
            const int kk = ks * 8;
            uint32_t a[2][4], b[4][2];
#pragma unroll
            for (int mi = 0; mi < 2; mi++) {
                int mb = wm + mi * 16;
                a[mi][0] = As[(mb + g4) * SA + kk + t4];
                a[mi][1] = As[(mb + g4 + 8) * SA + kk + t4];
                a[mi][2] = As[(mb + g4) * SA + kk + t4 + 4];
                a[mi][3] = As[(mb + g4 + 8) * SA + kk + t4 + 4];
            }
#pragma unroll
            for (int ni = 0; ni < 4; ni++) {
                int nb = wn + ni * 8 + g4;
                b[ni][0] = Bs[(kk + t4) * SB + nb];
                b[ni][1] = Bs[(kk + t4 + 4) * SB + nb];
            }
#pragma unroll
            for (int mi = 0; mi < 2; mi++)
#pragma unroll
                for (int ni = 0; ni < 4; ni++)
                    mma_tf32(c[mi][ni], a[mi][0], a[mi][1], a[mi][2], a[mi][3],
                             b[ni][0], b[ni][1]);
        }
    }

    // epilogue: bias + silu + store
#pragma unroll
    for (int mi = 0; mi < 2; mi++) {
#pragma unroll
        for (int ni = 0; ni < 4; ni++) {
            int n = n0 + wn + ni * 8 + 2 * t4;
            float bv0 = g_bcat[n], bv1 = g_bcat[n + 1];
            int r0 = m0 + wm + mi * 16 + g4;
            int r1 = r0 + 8;
            float2 o0 = make_float2(silu_f(c[mi][ni][0] + bv0), silu_f(c[mi][ni][1] + bv1));
            float2 o1 = make_float2(silu_f(c[mi][ni][2] + bv0), silu_f(c[mi][ni][3] + bv1));
            *reinterpret_cast<float2*>(&g_h[(size_t)r0 * NTOT + n]) = o0;
            *reinterpret_cast<float2*>(&g_h[(size_t)r1 * NTOT + n]) = o1;
        }
    }
}

// ================= tf32 tensor-core GEMM2 =================
// newe[E,64] = g_h[:, :256] @ W2[256,64] + b2 + edges0
__global__ void __launch_bounds__(256) gemm2_tc(const float* __restrict__ W2,
                                                const float* __restrict__ b2,
                                                const float* __restrict__ edges0,
                                                float* __restrict__ Cout)
{
    constexpr int LDA = NOUT1, KK = H1D, NTOT = OUTD;
    constexpr int SA = 36, SB = 72;
    __shared__ uint32_t As[128 * SA];
    __shared__ uint32_t Bs[32 * SB];

    const int t = threadIdx.x, lane = t & 31, wid = t >> 5;
    const int g4 = lane >> 2, t4 = lane & 3;
    const int wm = (wid & 3) * 32, wn = (wid >> 2) * 32;
    const int m0 = blockIdx.y * 128;

    float c[2][4][4];
#pragma unroll
    for (int mi = 0; mi < 2; mi++)
#pragma unroll
        for (int ni = 0; ni < 4; ni++)
#pragma unroll
            for (int q = 0; q < 4; q++) c[mi][ni][q] = 0.f;

    const float* Ap = g_h + (size_t)m0 * LDA;

    int arow[4], ac4[4];
#pragma unroll
    for (int i = 0; i < 4; i++) { int idx = t + 256 * i; arow[i] = idx >> 3; ac4[i] = idx & 7; }
    int brow[2], bc4[2];
#pragma unroll
    for (int i = 0; i < 2; i++) { int idx = t + 256 * i; brow[i] = idx >> 4; bc4[i] = idx & 15; }

    float4 areg[4], breg[2];
#pragma unroll
    for (int i = 0; i < 4; i++)
        areg[i] = *reinterpret_cast<const float4*>(&Ap[(size_t)arow[i] * LDA + ac4[i] * 4]);
#pragma unroll
    for (int i = 0; i < 2; i++)
        breg[i] = *reinterpret_cast<const float4*>(&W2[(size_t)brow[i] * NTOT + bc4[i] * 4]);

#pragma unroll 1
    for (int k0 = 0; k0 < KK; k0 += 32) {
        __syncthreads();
#pragma unroll
        for (int i = 0; i < 4; i++) {
            uint4 u = make_uint4(f2tf(areg[i].x), f2tf(areg[i].y), f2tf(areg[i].z), f2tf(areg[i].w));
            *reinterpret_cast<uint4*>(&As[arow[i] * SA + ac4[i] * 4]) = u;
        }
#pragma unroll
        for (int i = 0; i < 2; i++) {
            uint4 u = make_uint4(f2tf(breg[i].x), f2tf(breg[i].y), f2tf(breg[i].z), f2tf(breg[i].w));
            *reinterpret_cast<uint4*>(&Bs[brow[i] * SB + bc4[i] * 4]) = u;
        }
        __syncthreads();

        if (k0 + 32 < KK) {
#pragma unroll
            for (int i = 0; i < 4; i++)
                areg[i] = *reinterpret_cast<const float4*>(&Ap[(size_t)arow[i] * LDA + k0 + 32 + ac4[i] * 4]);
#pragma unroll
            for (int i = 0; i < 2; i++)
                breg[i] = *reinterpret_cast<const float4*>(&W2[(size_t)(k0 + 32 + brow[i]) * NTOT + bc4[i] * 4]);
        }

#pragma unroll
        for (int ks = 0; ks < 4; ks++) {
            const int kk = ks * 8;
            uint32_t a[2][4], b[4][2];
#pragma unroll
            for (int mi = 0; mi < 2; mi++) {
                int mb = wm + mi * 16;
                a[mi][0] = As[(mb + g4) * SA + kk + t4];
                a[mi][1] = As[(mb + g4 + 8) * SA + kk + t4];
                a[mi][2] = As[(mb + g4) * SA + kk + t4 + 4];
                a[mi][3] = As[(mb + g4 + 8) * SA + kk + t4 + 4];
            }
#pragma unroll
            for (int ni = 0; ni < 4; ni++) {
                int nb = wn + ni * 8 + g4;
                b[ni][0] = Bs[(kk + t4) * SB + nb];
                b[ni][1] = Bs[(kk + t4 + 4) * SB + nb];
            }
#pragma unroll
            for (int mi = 0; mi < 2; mi++)
#pragma unroll
                for (int ni = 0; ni < 4; ni++)
                    mma_tf32(c[mi][ni], a[mi][0], a[mi][1], a[mi][2], a[mi][3],
                             b[ni][0], b[ni][1]);
        }
    }

    // epilogue: bias + residual(edges0) + store
#pragma unroll
    for (int mi = 0; mi < 2; mi++) {
#pragma unroll
        for (int ni = 0; ni < 4; ni++) {
            int n = wn + ni * 8 + 2 * t4;
            float bv0 = b2[n], bv1 = b2[n + 1];
            int r0 = m0 + wm + mi * 16 + g4;
            int r1 = r0 + 8;
            float2 e0 = *reinterpret_cast<const float2*>(&edges0[(size_t)r0 * NTOT + n]);
            float2 e1 = *reinterpret_cast<const float2*>(&edges0[(size_t)r1 * NTOT + n]);
            float2 o0 = make_float2(c[mi][ni][0] + bv0 + e0.x, c[mi][ni][1] + bv1 + e0.y);
            float2 o1 = make_float2(c[mi][ni][2] + bv0 + e1.x, c[mi][ni][3] + bv1 + e1.y);
            *reinterpret_cast<float2*>(&Cout[(size_t)r0 * NTOT + n]) = o0;
            *reinterpret_cast<float2*>(&Cout[(size_t)r1 * NTOT + n]) = o1;
        }
    }
}

// ---------------- K4: attention logits, exp, denom ----------------
__global__ void attn_logits_kernel(const float* __restrict__ A2, const float* __restrict__ ab2,
                                   const int* __restrict__ bidx, const int* __restrict__ ridx)
{
    __shared__ float sA2[AHD * NH];
    int t = threadIdx.x;
    if (t < AHD * NH) sA2[t] = A2[t];
    __syncthreads();

    int e = blockIdx.x * blockDim.x + t;
    if (e >= EDG) return;
    const float* hr = g_h + (size_t)e * NOUT1 + H1D;

    float acc[NH] = {ab2[0], ab2[1], ab2[2], ab2[3]};
#pragma unroll
    for (int q = 0; q < AHD / 4; q++) {
        float4 v4 = *reinterpret_cast<const float4*>(&hr[q * 4]);
        float v[4] = {v4.x, v4.y, v4.z, v4.w};
#pragma unroll
        for (int u = 0; u < 4; u++) {
            int j = q * 4 + u;
#pragma unroll
            for (int h = 0; h < NH; h++)
                acc[h] = fmaf(v[u], sA2[j * NH + h], acc[h]);
        }
    }
    int seg = bidx[e] * NNODE + ridx[e];
#pragma unroll
    for (int h = 0; h < NH; h++) {
        float ae = __expf(acc[h] * 0.125f);
        g_ae[e * NH + h] = ae;
        atomicAdd(&g_den[seg * NH + h], ae);
    }
}

__global__ void invden_kernel()
{
    int i = blockIdx.x * blockDim.x + threadIdx.x;
    if (i < NSEG * NH) {
        float d = g_den[i];
        g_invden[i] = (d > 0.f) ? (1.f / d) : 0.f;
    }
}

// ---------------- K5: pooled scatter ----------------
__global__ void pool_kernel(const int* __restrict__ bidx, const int* __restrict__ ridx,
                            const float* __restrict__ newe, float* __restrict__ pooled)
{
    int gid = blockIdx.x * blockDim.x + threadIdx.x;
    int e = gid >> 6;
    int c = gid & 63;
    int seg = bidx[e] * NNODE + ridx[e];
    int h = c >> 4;
    float attn = g_ae[e * NH + h] * g_invden[seg * NH + h];
    atomicAdd(&pooled[seg * OUTD + c], newe[gid] * attn);
}

// ---------------- entry ----------------
extern "C" void kernel_launch(void* const* d_in, const int* in_sizes, int n_in,
                              void* d_out, int out_size)
{
    const float* nodes  = (const float*)d_in[0];
    const float* edges0 = (const float*)d_in[1];
    const float* globs  = (const float*)d_in[2];
    const float* ln_g   = (const float*)d_in[3];
    const float* ln_b   = (const float*)d_in[4];
    const float* W1     = (const float*)d_in[5];
    const float* b1     = (const float*)d_in[6];
    const float* W2     = (const float*)d_in[7];
    const float* b2     = (const float*)d_in[8];
    const float* A1     = (const float*)d_in[9];
    const float* ab1    = (const float*)d_in[10];
    const float* A2     = (const float*)d_in[11];
    const float* ab2    = (const float*)d_in[12];
    const int*   bidx   = (const int*)d_in[13];
    const int*   sidx   = (const int*)d_in[14];
    const int*   ridx   = (const int*)d_in[15];

    float* out    = (float*)d_out;
    float* newe   = out;
    float* pooled = out + (size_t)EDG * OUTD;

    prep_kernel<<<(NSEG * OUTD + 255) / 256, 256>>>(W1, b1, A1, ab1, pooled);
    build_x_kernel<<<EDG / 8, 256>>>(nodes, edges0, globs, ln_g, ln_b, bidx, sidx, ridx);
    gemm1_tc<<<dim3(NOUT1 / 64, EDG / 128), 256>>>();
    gemm2_tc<<<dim3(1, EDG / 128), 256>>>(W2, b2, edges0, newe);
    attn_logits_kernel<<<EDG / 256, 256>>>(A2, ab2, bidx, ridx);
    invden_kernel<<<(NSEG * NH + 255) / 256, 256>>>();
    pool_kernel<<<(EDG * OUTD) / 256, 256>>>(bidx, ridx, newe, pooled);
}

// round 8
// speedup vs baseline: 2.3046x; 1.0031x over previous
#include <cuda_runtime.h>
#include <math.h>
#include <stdint.h>

// ---------------- problem constants ----------------
#define EDG   262144
#define BGR   8
#define NNODE 512
#define NDIM  128
#define EDIM  64
#define GDIM  32
#define FIN   320
#define XDIM  352
#define H1D   256
#define AHD   64
#define NOUT1 320
#define OUTD  64
#define NH    4
#define NSEG  (BGR*NNODE)

// ---------------- device scratch ----------------
__device__ float  g_h[(size_t)EDG * H1D];      // MLP hidden only (attn cols never stored)
__device__ float  g_Wcat[XDIM * NOUT1];
__device__ float  g_bcat[NOUT1];
__device__ float2 g_stats[EDG];                // (mu, rstd) per edge
__device__ float  g_ae[EDG * NH];
__device__ float  g_den[NSEG * NH];
__device__ float  g_invden[NSEG * NH];

// ---------------- helpers ----------------
__device__ __forceinline__ uint32_t f2tf(float f) {
    uint32_t r;
    asm("cvt.rna.tf32.f32 %0, %1;" : "=r"(r) : "f"(f));
    return r;
}
__device__ __forceinline__ void mma_tf32(float c[4],
                                         uint32_t a0, uint32_t a1, uint32_t a2, uint32_t a3,
                                         uint32_t b0, uint32_t b1)
{
    asm volatile(
        "mma.sync.aligned.m16n8k8.row.col.f32.tf32.tf32.f32 "
        "{%0,%1,%2,%3}, {%4,%5,%6,%7}, {%8,%9}, {%0,%1,%2,%3};"
        : "+f"(c[0]), "+f"(c[1]), "+f"(c[2]), "+f"(c[3])
        : "r"(a0), "r"(a1), "r"(a2), "r"(a3), "r"(b0), "r"(b1));
}
__device__ __forceinline__ float silu_f(float v) { return v / (1.f + __expf(-v)); }

// ---------------- prep: pack weights, zero accumulators ----------------
__global__ void prep_kernel(const float* __restrict__ W1, const float* __restrict__ b1,
                            const float* __restrict__ A1, const float* __restrict__ ab1,
                            float* __restrict__ pooled)
{
    int i = blockIdx.x * blockDim.x + threadIdx.x;
    if (i < XDIM * NOUT1) {
        int k = i / NOUT1, n = i % NOUT1;
        g_Wcat[i] = (n < H1D) ? W1[k * H1D + n] : A1[k * AHD + (n - H1D)];
    }
    if (i < NOUT1) g_bcat[i] = (i < H1D) ? b1[i] : ab1[i - H1D];
    if (i < NSEG * NH) g_den[i] = 0.f;
    if (i < NSEG * OUTD) pooled[i] = 0.f;
}

// ---------------- stats: per-edge LayerNorm mu/rstd ----------------
__global__ void stats_kernel(const float* __restrict__ nodes,
                             const float* __restrict__ edges0,
                             const int* __restrict__ bidx,
                             const int* __restrict__ sidx,
                             const int* __restrict__ ridx)
{
    int e = blockIdx.x * (blockDim.x >> 5) + (threadIdx.x >> 5);
    int lane = threadIdx.x & 31;
    if (e >= EDG) return;
    int b = bidx[e], s = sidx[e], r = ridx[e];
    const float* srow = nodes + ((size_t)b * NNODE + s) * NDIM;
    const float* rrow = nodes + ((size_t)b * NNODE + r) * NDIM;
    const float* erow = edges0 + (size_t)e * EDIM;

    float v[10];
    v[0] = erow[lane];
    v[1] = erow[lane + 32];
#pragma unroll
    for (int i = 0; i < 4; i++) v[2 + i] = srow[lane + 32 * i];
#pragma unroll
    for (int i = 0; i < 4; i++) v[6 + i] = rrow[lane + 32 * i];

    float s1 = 0.f, s2 = 0.f;
#pragma unroll
    for (int i = 0; i < 10; i++) { s1 += v[i]; s2 += v[i] * v[i]; }
#pragma unroll
    for (int off = 16; off > 0; off >>= 1) {
        s1 += __shfl_xor_sync(0xffffffffu, s1, off);
        s2 += __shfl_xor_sync(0xffffffffu, s2, off);
    }
    if (lane == 0) {
        float mu  = s1 * (1.f / FIN);
        float var = s2 * (1.f / FIN) - mu * mu;
        g_stats[e] = make_float2(mu, rsqrtf(var + 1e-5f));
    }
}

// ================= fused gather+LN+GEMM1 (+attn logits on block x==4) =================
// out = silu([LN(gather)|globs] @ [W1|A1] + [b1|ab1]); blocks x=0..3 -> g_h[E,256];
// block x==4 computes attn logits -> g_ae, g_den (no store of attn hidden).
__global__ void __launch_bounds__(256) gemm1_fused(const float* __restrict__ nodes,
                                                   const float* __restrict__ edges0,
                                                   const float* __restrict__ globs,
                                                   const float* __restrict__ ln_g,
                                                   const float* __restrict__ ln_b,
                                                   const int* __restrict__ bidx,
                                                   const int* __restrict__ sidx,
                                                   const int* __restrict__ ridx,
                                                   const float* __restrict__ A2,
                                                   const float* __restrict__ ab2)
{
    constexpr int KK = XDIM, NTOT = NOUT1;
    constexpr int SA = 36, SB = 72;
    __shared__ uint32_t As[128 * SA];
    __shared__ uint32_t Bs[32 * SB];
    __shared__ float    slog[128][NH];

    const int t = threadIdx.x, lane = t & 31, wid = t >> 5;
    const int g4 = lane >> 2, t4 = lane & 3;
    const int wm = (wid & 3) * 32, wn = (wid >> 2) * 32;
    const int m0 = blockIdx.y * 128, n0 = blockIdx.x * 64;
    const bool is_attn = (blockIdx.x == 4);

    float c[2][4][4];
#pragma unroll
    for (int mi = 0; mi < 2; mi++)
#pragma unroll
        for (int ni = 0; ni < 4; ni++)
#pragma unroll
            for (int q = 0; q < 4; q++) c[mi][ni][q] = 0.f;

    // ---- per-row gather metadata (rows e0 + 32*i, same ac4 for all i) ----
    const int ac4 = t & 7;              // col group within 32-wide k tile
    const int r0l = t >> 3;             // local row base (0..31)
    int  soff[4], roff[4], goff[4];
    float mu[4], rs[4];
#pragma unroll
    for (int i = 0; i < 4; i++) {
        int e = m0 + r0l + 32 * i;
        int b = bidx[e];
        soff[i] = (b * NNODE + sidx[e]) * NDIM;
        roff[i] = (b * NNODE + ridx[e]) * NDIM;
        goff[i] = b * GDIM;
        float2 st = g_stats[e];
        mu[i] = st.x; rs[i] = st.y;
    }

    int brow[2], bc4[2];
#pragma unroll
    for (int i = 0; i < 2; i++) { int idx = t + 256 * i; brow[i] = idx >> 4; bc4[i] = idx & 15; }

    // ---- fetch helper (reads stage k0 into registers) ----
    float4 areg[4], breg[2], lg4, lb4;
#define FETCH_STAGE(K0)                                                                   \
    {                                                                                     \
        int kq = (K0) + ac4 * 4;                                                          \
        if ((K0) < 64) {                                                                  \
            _Pragma("unroll")                                                             \
            for (int i = 0; i < 4; i++)                                                   \
                areg[i] = *reinterpret_cast<const float4*>(                               \
                    &edges0[(size_t)(m0 + r0l + 32 * i) * EDIM + kq]);                    \
        } else if ((K0) < 192) {                                                          \
            _Pragma("unroll")                                                             \
            for (int i = 0; i < 4; i++)                                                   \
                areg[i] = *reinterpret_cast<const float4*>(&nodes[soff[i] + kq - 64]);    \
        } else if ((K0) < 320) {                                                          \
            _Pragma("unroll")                                                             \
            for (int i = 0; i < 4; i++)                                                   \
                areg[i] = *reinterpret_cast<const float4*>(&nodes[roff[i] + kq - 192]);   \
        } else {                                                                          \
            _Pragma("unroll")                                                             \
            for (int i = 0; i < 4; i++)                                                   \
                areg[i] = *reinterpret_cast<const float4*>(&globs[goff[i] + kq - 320]);   \
        }                                                                                 \
        if ((K0) < 320) {                                                                 \
            lg4 = *reinterpret_cast<const float4*>(&ln_g[kq]);                            \
            lb4 = *reinterpret_cast<const float4*>(&ln_b[kq]);                            \
        }                                                                                 \
        _Pragma("unroll")                                                                 \
        for (int i = 0; i < 2; i++)                                                       \
            breg[i] = *reinterpret_cast<const float4*>(                                   \
                &g_Wcat[(size_t)((K0) + brow[i]) * NTOT + n0 + bc4[i] * 4]);              \
    }

    FETCH_STAGE(0);

#pragma unroll 1
    for (int k0 = 0; k0 < KK; k0 += 32) {
        __syncthreads();
        // stage A (apply LN for k0<320)
        if (k0 < 320) {
#pragma unroll
            for (int i = 0; i < 4; i++) {
                float x0 = (areg[i].x - mu[i]) * rs[i] * lg4.x + lb4.x;
                float x1 = (areg[i].y - mu[i]) * rs[i] * lg4.y + lb4.y;
                float x2 = (areg[i].z - mu[i]) * rs[i] * lg4.z + lb4.z;
                float x3 = (areg[i].w - mu[i]) * rs[i] * lg4.w + lb4.w;
                *reinterpret_cast<uint4*>(&As[(r0l + 32 * i) * SA + ac4 * 4]) =
                    make_uint4(f2tf(x0), f2tf(x1), f2tf(x2), f2tf(x3));
            }
        } else {
#pragma unroll
            for (int i = 0; i < 4; i++)
                *reinterpret_cast<uint4*>(&As[(r0l + 32 * i) * SA + ac4 * 4]) =
                    make_uint4(f2tf(areg[i].x), f2tf(areg[i].y), f2tf(areg[i].z), f2tf(areg[i].w));
        }
#pragma unroll
        for (int i = 0; i < 2; i++)
            *reinterpret_cast<uint4*>(&Bs[brow[i] * SB + bc4[i] * 4]) =
                make_uint4(f2tf(breg[i].x), f2tf(breg[i].y), f2tf(breg[i].z), f2tf(breg[i].w));
        __syncthreads();

        if (k0 + 32 < KK) {
            switch (k0 + 32) {          // compile-time-ish dispatch keeps branches cheap
                case 32:  FETCH_STAGE(32);  break;
                case 64:  FETCH_STAGE(64);  break;
                case 96:  FETCH_STAGE(96);  break;
                case 128: FETCH_STAGE(128); break;
                case 160: FETCH_STAGE(160); break;
                case 192: FETCH_STAGE(192); break;
                case 224: FETCH_STAGE(224); break;
                case 256: FETCH_STAGE(256); break;
                case 288: FETCH_STAGE(288); break;
                default:  FETCH_STAGE(320); break;
            }
        }

#pragma unroll
        for (int ks = 0; ks < 4; ks++) {
            const int kk = ks * 8;
            uint32_t a[2][4], b[4][2];
#pragma unroll
            for (int mi = 0; mi < 2; mi++) {
                int mb = wm + mi * 16;
                a[mi][0] = As[(mb + g4) * SA + kk + t4];
                a[mi][1] = As[(mb + g4 + 8) * SA + kk + t4];
                a[mi][2] = As[(mb + g4) * SA + kk + t4 + 4];
                a[mi][3] = As[(mb + g4 + 8) * SA + kk + t4 + 4];
            }
#pragma unroll
            for (int ni = 0; ni < 4; ni++) {
                int nb = wn + ni * 8 + g4;
                b[ni][0] = Bs[(kk + t4) * SB + nb];
                b[ni][1] = Bs[(kk + t4 + 4) * SB + nb];
            }
#pragma unroll
            for (int mi = 0; mi < 2; mi++)
#pragma unroll
                for (int ni = 0; ni < 4; ni++)
                    mma_tf32(c[mi][ni], a[mi][0], a[mi][1], a[mi][2], a[mi][3],
                             b[ni][0], b[ni][1]);
        }
    }
#undef FETCH_STAGE

    if (!is_attn) {
        // epilogue: bias + silu -> g_h[E,256]
#pragma unroll
        for (int mi = 0; mi < 2; mi++) {
#pragma unroll
            for (int ni = 0; ni < 4; ni++) {
                int n = n0 + wn + ni * 8 + 2 * t4;
                float bv0 = g_bcat[n], bv1 = g_bcat[n + 1];
                int rr0 = m0 + wm + mi * 16 + g4;
                int rr1 = rr0 + 8;
                *reinterpret_cast<float2*>(&g_h[(size_t)rr0 * H1D + n]) =
                    make_float2(silu_f(c[mi][ni][0] + bv0), silu_f(c[mi][ni][1] + bv1));
                *reinterpret_cast<float2*>(&g_h[(size_t)rr1 * H1D + n]) =
                    make_float2(silu_f(c[mi][ni][2] + bv0), silu_f(c[mi][ni][3] + bv1));
            }
        }
    } else {
        // epilogue: attn logits = silu(h_attn) @ A2, exp, denom atomics
        if (t < 128) *reinterpret_cast<float4*>(&slog[t][0]) = make_float4(0.f, 0.f, 0.f, 0.f);
        __syncthreads();

        float pl[2][2][NH];
#pragma unroll
        for (int mi = 0; mi < 2; mi++)
#pragma unroll
            for (int hf = 0; hf < 2; hf++)
#pragma unroll
                for (int h = 0; h < NH; h++) pl[mi][hf][h] = 0.f;

#pragma unroll
        for (int mi = 0; mi < 2; mi++) {
#pragma unroll
            for (int ni = 0; ni < 4; ni++) {
                int n = wn + ni * 8 + 2 * t4;          // attn-local col 0..63
                float bv0 = g_bcat[H1D + n], bv1 = g_bcat[H1D + n + 1];
                float v00 = silu_f(c[mi][ni][0] + bv0);
                float v01 = silu_f(c[mi][ni][1] + bv1);
                float v10 = silu_f(c[mi][ni][2] + bv0);
                float v11 = silu_f(c[mi][ni][3] + bv1);
                float4 a20 = *reinterpret_cast<const float4*>(&A2[n * NH]);
                float4 a21 = *reinterpret_cast<const float4*>(&A2[(n + 1) * NH]);
                pl[mi][0][0] += v00 * a20.x + v01 * a21.x;
                pl[mi][0][1] += v00 * a20.y + v01 * a21.y;
                pl[mi][0][2] += v00 * a20.z + v01 * a21.z;
                pl[mi][0][3] += v00 * a20.w + v01 * a21.w;
                pl[mi][1][0] += v10 * a20.x + v11 * a21.x;
                pl[mi][1][1] += v10 * a20.y + v11 * a21.y;
                pl[mi][1][2] += v10 * a20.z + v11 * a21.z;
                pl[mi][1][3] += v10 * a20.w + v11 * a21.w;
            }
        }
#pragma unroll
        for (int mi = 0; mi < 2; mi++)
#pragma unroll
            for (int hf = 0; hf < 2; hf++) {
                int rl = wm + mi * 16 + g4 + hf * 8;
#pragma unroll
                for (int h = 0; h < NH; h++)
                    atomicAdd(&slog[rl][h], pl[mi][hf][h]);
            }
        __syncthreads();

        if (t < 128) {
            int e = m0 + t;
            float4 l = *reinterpret_cast<float4*>(&slog[t][0]);
            float ae0 = __expf((l.x + ab2[0]) * 0.125f);
            float ae1 = __expf((l.y + ab2[1]) * 0.125f);
            float ae2 = __expf((l.z + ab2[2]) * 0.125f);
            float ae3 = __expf((l.w + ab2[3]) * 0.125f);
            *reinterpret_cast<float4*>(&g_ae[(size_t)e * NH]) = make_float4(ae0, ae1, ae2, ae3);
            int seg = bidx[e] * NNODE + ridx[e];
            atomicAdd(&g_den[seg * NH + 0], ae0);
            atomicAdd(&g_den[seg * NH + 1], ae1);
            atomicAdd(&g_den[seg * NH + 2], ae2);
            atomicAdd(&g_den[seg * NH + 3], ae3);
        }
    }
}

__global__ void invden_kernel()
{
    int i = blockIdx.x * blockDim.x + threadIdx.x;
    if (i < NSEG * NH) {
        float d = g_den[i];
        g_invden[i] = (d > 0.f) ? (1.f / d) : 0.f;
    }
}

// ================= GEMM2 + residual + fused attention-weighted pool =================
// newe = g_h[E,256] @ W2 + b2 + edges0 ; pooled[seg] += newe * attn  (atomics)
__global__ void __launch_bounds__(256) gemm2_fused(const float* __restrict__ W2,
                                                   const float* __restrict__ b2,
                                                   const float* __restrict__ edges0,
                                                   const int* __restrict__ bidx,
                                                   const int* __restrict__ ridx,
                                                   float* __restrict__ Cout,
                                                   float* __restrict__ pooled)
{
    constexpr int LDA = H1D, KK = H1D, NTOT = OUTD;
    constexpr int SA = 36, SB = 72;
    __shared__ uint32_t As[128 * SA];
    __shared__ uint32_t Bs[32 * SB];

    const int t = threadIdx.x, lane = t & 31, wid = t >> 5;
    const int g4 = lane >> 2, t4 = lane & 3;
    const int wm = (wid & 3) * 32, wn = (wid >> 2) * 32;
    const int m0 = blockIdx.y * 128;

    float c[2][4][4];
#pragma unroll
    for (int mi = 0; mi < 2; mi++)
#pragma unroll
        for (int ni = 0; ni < 4; ni++)
#pragma unroll
            for (int q = 0; q < 4; q++) c[mi][ni][q] = 0.f;

    const float* Ap = g_h + (size_t)m0 * LDA;

    int arow[4], ac4[4];
#pragma unroll
    for (int i = 0; i < 4; i++) { int idx = t + 256 * i; arow[i] = idx >> 3; ac4[i] = idx & 7; }
    int brow[2], bc4[2];
#pragma unroll
    for (int i = 0; i < 2; i++) { int idx = t + 256 * i; brow[i] = idx >> 4; bc4[i] = idx & 15; }

    float4 areg[4], breg[2];
#pragma unroll
    for (int i = 0; i < 4; i++)
        areg[i] = *reinterpret_cast<const float4*>(&Ap[(size_t)arow[i] * LDA + ac4[i] * 4]);
#pragma unroll
    for (int i = 0; i < 2; i++)
        breg[i] = *reinterpret_cast<const float4*>(&W2[(size_t)brow[i] * NTOT + bc4[i] * 4]);

#pragma unroll 1
    for (int k0 = 0; k0 < KK; k0 += 32) {
        __syncthreads();
#pragma unroll
        for (int i = 0; i < 4; i++)
            *reinterpret_cast<uint4*>(&As[arow[i] * SA + ac4[i] * 4]) =
                make_uint4(f2tf(areg[i].x), f2tf(areg[i].y), f2tf(areg[i].z), f2tf(areg[i].w));
#pragma unroll
        for (int i = 0; i < 2; i++)
            *reinterpret_cast<uint4*>(&Bs[brow[i] * SB + bc4[i] * 4]) =
                make_uint4(f2tf(breg[i].x), f2tf(breg[i].y), f2tf(breg[i].z), f2tf(breg[i].w));
        __syncthreads();

        if (k0 + 32 < KK) {
#pragma unroll
            for (int i = 0; i < 4; i++)
                areg[i] = *reinterpret_cast<const float4*>(&Ap[(size_t)arow[i] * LDA + k0 + 32 + ac4[i] * 4]);
#pragma unroll
            for (int i = 0; i < 2; i++)
                breg[i] = *reinterpret_cast<const float4*>(&W2[(size_t)(k0 + 32 + brow[i]) * NTOT + bc4[i] * 4]);
        }

#pragma unroll
        for (int ks = 0; ks < 4; ks++) {
            const int kk = ks * 8;
            uint32_t a[2][4], b[4][2];
#pragma unroll
            for (int mi = 0; mi < 2; mi++) {
                int mb = wm + mi * 16;
                a[mi][0] = As[(mb + g4) * SA + kk + t4];
                a[mi][1] = As[(mb + g4 + 8) * SA + kk + t4];
                a[mi][2] = As[(mb + g4) * SA + kk + t4 + 4];
                a[mi][3] = As[(mb + g4 + 8) * SA + kk + t4 + 4];
            }
#pragma unroll
            for (int ni = 0; ni < 4; ni++) {
                int nb = wn + ni * 8 + g4;
                b[ni][0] = Bs[(kk + t4) * SB + nb];
                b[ni][1] = Bs[(kk + t4 + 4) * SB + nb];
            }
#pragma unroll
            for (int mi = 0; mi < 2; mi++)
#pragma unroll
                for (int ni = 0; ni < 4; ni++)
                    mma_tf32(c[mi][ni], a[mi][0], a[mi][1], a[mi][2], a[mi][3],
                             b[ni][0], b[ni][1]);
        }
    }

    // per-row attention weights (4 rows per thread)
    int   segr[2][2];
    float aw[2][2][NH];
#pragma unroll
    for (int mi = 0; mi < 2; mi++)
#pragma unroll
        for (int hf = 0; hf < 2; hf++) {
            int r = m0 + wm + mi * 16 + g4 + hf * 8;
            int seg = bidx[r] * NNODE + ridx[r];
            segr[mi][hf] = seg;
            float4 ae4 = *reinterpret_cast<const float4*>(&g_ae[(size_t)r * NH]);
            float4 iv4 = *reinterpret_cast<const float4*>(&g_invden[(size_t)seg * NH]);
            aw[mi][hf][0] = ae4.x * iv4.x;
            aw[mi][hf][1] = ae4.y * iv4.y;
            aw[mi][hf][2] = ae4.z * iv4.z;
            aw[mi][hf][3] = ae4.w * iv4.w;
        }

    // epilogue: bias + residual -> Cout; attention-weighted atomics -> pooled
#pragma unroll
    for (int mi = 0; mi < 2; mi++) {
#pragma unroll
        for (int ni = 0; ni < 4; ni++) {
            int n = wn + ni * 8 + 2 * t4;
            int h = n >> 4;                    // n even -> n and n+1 share a head
            float bv0 = b2[n], bv1 = b2[n + 1];
            int rr0 = m0 + wm + mi * 16 + g4;
            int rr1 = rr0 + 8;
            float2 e0 = *reinterpret_cast<const float2*>(&edges0[(size_t)rr0 * NTOT + n]);
            float2 e1 = *reinterpret_cast<const float2*>(&edges0[(size_t)rr1 * NTOT + n]);
            float o00 = c[mi][ni][0] + bv0 + e0.x;
            float o01 = c[mi][ni][1] + bv1 + e0.y;
            float o10 = c[mi][ni][2] + bv0 + e1.x;
            float o11 = c[mi][ni][3] + bv1 + e1.y;
            *reinterpret_cast<float2*>(&Cout[(size_t)rr0 * NTOT + n]) = make_float2(o00, o01);
            *reinterpret_cast<float2*>(&Cout[(size_t)rr1 * NTOT + n]) = make_float2(o10, o11);
            float w0 = aw[mi][0][h], w1 = aw[mi][1][h];
            atomicAdd(&pooled[(size_t)segr[mi][0] * OUTD + n],     o00 * w0);
            atomicAdd(&pooled[(size_t)segr[mi][0] * OUTD + n + 1], o01 * w0);
            atomicAdd(&pooled[(size_t)segr[mi][1] * OUTD + n],     o10 * w1);
            atomicAdd(&pooled[(size_t)segr[mi][1] * OUTD + n + 1], o11 * w1);
        }
    }
}

// ---------------- entry ----------------
extern "C" void kernel_launch(void* const* d_in, const int* in_sizes, int n_in,
                              void* d_out, int out_size)
{
    const float* nodes  = (const float*)d_in[0];
    const float* edges0 = (const float*)d_in[1];
    const float* globs  = (const float*)d_in[2];
    const float* ln_g   = (const float*)d_in[3];
    const float* ln_b   = (const float*)d_in[4];
    const float* W1     = (const float*)d_in[5];
    const float* b1     = (const float*)d_in[6];
    const float* W2     = (const float*)d_in[7];
    const float* b2     = (const float*)d_in[8];
    const float* A1     = (const float*)d_in[9];
    const float* ab1    = (const float*)d_in[10];
    const float* A2     = (const float*)d_in[11];
    const float* ab2    = (const float*)d_in[12];
    const int*   bidx   = (const int*)d_in[13];
    const int*   sidx   = (const int*)d_in[14];
    const int*   ridx   = (const int*)d_in[15];

    float* out    = (float*)d_out;
    float* newe   = out;
    float* pooled = out + (size_t)EDG * OUTD;

    prep_kernel<<<(NSEG * OUTD + 255) / 256, 256>>>(W1, b1, A1, ab1, pooled);
    stats_kernel<<<EDG / 8, 256>>>(nodes, edges0, bidx, sidx, ridx);
    gemm1_fused<<<dim3(5, EDG / 128), 256>>>(nodes, edges0, globs, ln_g, ln_b,
                                             bidx, sidx, ridx, A2, ab2);
    invden_kernel<<<(NSEG * NH + 255) / 256, 256>>>();
    gemm2_fused<<<dim3(1, EDG / 128), 256>>>(W2, b2, edges0, bidx, ridx, newe, pooled);
}

// round 9
// speedup vs baseline: 2.5353x; 1.1001x over previous
#include <cuda_runtime.h>
#include <math.h>
#include <stdint.h>

// ---------------- problem constants ----------------
#define EDG   262144
#define BGR   8
#define NNODE 512
#define NDIM  128
#define EDIM  64
#define GDIM  32
#define FIN   320
#define H1D   256
#define AHD   64
#define KW    320            // GEMM1 K after LN-fold (feats only)
#define NW    320            // GEMM1 N (H1D + AHD)
#define OUTD  64
#define NH    4
#define NSEG  (BGR*NNODE)

// ---------------- device scratch ----------------
__device__ uint32_t g_h[(size_t)EDG * H1D];    // silu hidden as tf32 bits
__device__ uint32_t g_Wtf[KW * NW];            // ln_g-scaled [W1|A1], tf32 bits
__device__ uint32_t g_W2tf[H1D * OUTD];        // W2, tf32 bits
__device__ float    g_u[NW];                   // col sums of scaled weights
__device__ float    g_vb[NW];                  // ln_b@W + bias
__device__ float    g_gg[BGR * NW];            // globs@W_glob per graph
__device__ float    g_ae[EDG * NH];
__device__ float    g_den[NSEG * NH];
__device__ float    g_invden[NSEG * NH];

// ---------------- helpers ----------------
__device__ __forceinline__ uint32_t f2tf(float f) {
    uint32_t r;
    asm("cvt.rna.tf32.f32 %0, %1;" : "=r"(r) : "f"(f));
    return r;
}
__device__ __forceinline__ void mma_tf32(float c[4],
                                         uint32_t a0, uint32_t a1, uint32_t a2, uint32_t a3,
                                         uint32_t b0, uint32_t b1)
{
    asm volatile(
        "mma.sync.aligned.m16n8k8.row.col.f32.tf32.tf32.f32 "
        "{%0,%1,%2,%3}, {%4,%5,%6,%7}, {%8,%9}, {%0,%1,%2,%3};"
        : "+f"(c[0]), "+f"(c[1]), "+f"(c[2]), "+f"(c[3])
        : "r"(a0), "r"(a1), "r"(a2), "r"(a3), "r"(b0), "r"(b1));
}
__device__ __forceinline__ float silu_f(float v) { return v / (1.f + __expf(-v)); }

// Wcat accessor on original inputs: rows k in [0,352), cols n in [0,320)
__device__ __forceinline__ float wcat(const float* W1, const float* A1, int k, int n) {
    return (n < H1D) ? W1[k * H1D + n] : A1[k * AHD + (n - H1D)];
}

// ---------------- prep: convert weights to tf32 bits, zero accumulators ----------------
__global__ void prep_kernel(const float* __restrict__ W1, const float* __restrict__ A1,
                            const float* __restrict__ W2, const float* __restrict__ ln_g,
                            float* __restrict__ pooled)
{
    int i = blockIdx.x * blockDim.x + threadIdx.x;
    if (i < KW * NW) {
        int k = i / NW, n = i % NW;
        g_Wtf[i] = f2tf(ln_g[k] * wcat(W1, A1, k, n));
    }
    if (i < H1D * OUTD) g_W2tf[i] = f2tf(W2[i]);
    if (i < NSEG * NH) g_den[i] = 0.f;
    if (i < NSEG * OUTD) pooled[i] = 0.f;
}

// ---------------- prep2: LN-fold correction tables ----------------
__global__ void prep2_kernel(const float* __restrict__ W1, const float* __restrict__ A1,
                             const float* __restrict__ b1, const float* __restrict__ ab1,
                             const float* __restrict__ ln_g, const float* __restrict__ ln_b,
                             const float* __restrict__ globs)
{
    int n = threadIdx.x;
    if (n >= NW) return;
    float u = 0.f, vb = 0.f;
    for (int k = 0; k < KW; k++) {
        float w = wcat(W1, A1, k, n);
        u  += ln_g[k] * w;
        vb += ln_b[k] * w;
    }
    vb += (n < H1D) ? b1[n] : ab1[n - H1D];
    g_u[n] = u;
    g_vb[n] = vb;
    for (int b = 0; b < BGR; b++) {
        float s = 0.f;
        for (int j = 0; j < GDIM; j++)
            s += globs[b * GDIM + j] * wcat(W1, A1, KW + j, n);
        g_gg[b * NW + n] = s;
    }
}

// ================= fused gather + GEMM1 (LN folded) =================
// blocks x=0..3: g_h[E,256] = tf32bits(silu(...)); block x==4: attn logits -> g_ae, g_den
__global__ void __launch_bounds__(256) gemm1_fused(const float* __restrict__ nodes,
                                                   const float* __restrict__ edges0,
                                                   const int* __restrict__ bidx,
                                                   const int* __restrict__ sidx,
                                                   const int* __restrict__ ridx,
                                                   const float* __restrict__ A2,
                                                   const float* __restrict__ ab2)
{
    constexpr int SA = 36, SB = 72;
    __shared__ uint32_t As[128 * SA];
    __shared__ uint32_t Bs[32 * SB];
    __shared__ float2   sstat[128];
    __shared__ float    slog[128][NH];

    const int t = threadIdx.x, lane = t & 31, wid = t >> 5;
    const int g4 = lane >> 2, t4 = lane & 3;
    const int wm = (wid & 3) * 32, wn = (wid >> 2) * 32;
    const int m0 = blockIdx.y * 128, n0 = blockIdx.x * 64;
    const bool is_attn = (blockIdx.x == 4);

    float c[2][4][4];
#pragma unroll
    for (int mi = 0; mi < 2; mi++)
#pragma unroll
        for (int ni = 0; ni < 4; ni++)
#pragma unroll
            for (int q = 0; q < 4; q++) c[mi][ni][q] = 0.f;

    // per-row gather offsets (4 rows per thread, 8 threads per row)
    const int ac4 = t & 7;       // 16B chunk within 32-wide k-stage
    const int r0l = t >> 3;      // local row base 0..31
    int soff[4], roff[4];
#pragma unroll
    for (int i = 0; i < 4; i++) {
        int e = m0 + r0l + 32 * i;
        int b = bidx[e];
        soff[i] = (b * NNODE + sidx[e]) * NDIM;
        roff[i] = (b * NNODE + ridx[e]) * NDIM;
    }

    int brow[2], bc4[2];
#pragma unroll
    for (int i = 0; i < 2; i++) { int idx = t + 256 * i; brow[i] = idx >> 4; bc4[i] = idx & 15; }

    // raw-feature gather: regions [0,64)=edges0, [64,192)=send, [192,320)=recv
    auto ldA = [&](int k0, int i) -> float4 {
        int kq = k0 + ac4 * 4;
        const float* p;
        if (k0 < 64)        p = edges0 + (size_t)(m0 + r0l + 32 * i) * EDIM + kq;
        else if (k0 < 192)  p = nodes + soff[i] + (kq - 64);
        else                p = nodes + roff[i] + (kq - 192);
        return *reinterpret_cast<const float4*>(p);
    };

    float4 areg[4];
    uint4  breg[2];
    float  s1[4] = {0.f, 0.f, 0.f, 0.f}, s2[4] = {0.f, 0.f, 0.f, 0.f};

#pragma unroll
    for (int i = 0; i < 4; i++) areg[i] = ldA(0, i);
#pragma unroll
    for (int i = 0; i < 2; i++)
        breg[i] = *reinterpret_cast<const uint4*>(&g_Wtf[(size_t)brow[i] * NW + n0 + bc4[i] * 4]);

#pragma unroll 1
    for (int k0 = 0; k0 < KW; k0 += 32) {
        __syncthreads();
#pragma unroll
        for (int i = 0; i < 4; i++) {
            float4 a = areg[i];
            s1[i] += a.x + a.y + a.z + a.w;
            s2[i] += a.x * a.x + a.y * a.y + a.z * a.z + a.w * a.w;
            *reinterpret_cast<uint4*>(&As[(r0l + 32 * i) * SA + ac4 * 4]) =
                make_uint4(f2tf(a.x), f2tf(a.y), f2tf(a.z), f2tf(a.w));
        }
#pragma unroll
        for (int i = 0; i < 2; i++)
            *reinterpret_cast<uint4*>(&Bs[brow[i] * SB + bc4[i] * 4]) = breg[i];
        __syncthreads();

        if (k0 + 32 < KW) {
#pragma unroll
            for (int i = 0; i < 4; i++) areg[i] = ldA(k0 + 32, i);
#pragma unroll
            for (int i = 0; i < 2; i++)
                breg[i] = *reinterpret_cast<const uint4*>(
                    &g_Wtf[(size_t)(k0 + 32 + brow[i]) * NW + n0 + bc4[i] * 4]);
        }

#pragma unroll
        for (int ks = 0; ks < 4; ks++) {
            const int kk = ks * 8;
            uint32_t a[2][4], b[4][2];
#pragma unroll
            for (int mi = 0; mi < 2; mi++) {
                int mb = wm + mi * 16;
                a[mi][0] = As[(mb + g4) * SA + kk + t4];
                a[mi][1] = As[(mb + g4 + 8) * SA + kk + t4];
                a[mi][2] = As[(mb + g4) * SA + kk + t4 + 4];
                a[mi][3] = As[(mb + g4 + 8) * SA + kk + t4 + 4];
            }
#pragma unroll
            for (int ni = 0; ni < 4; ni++) {
                int nb = wn + ni * 8 + g4;
                b[ni][0] = Bs[(kk + t4) * SB + nb];
                b[ni][1] = Bs[(kk + t4 + 4) * SB + nb];
            }
#pragma unroll
            for (int mi = 0; mi < 2; mi++)
#pragma unroll
                for (int ni = 0; ni < 4; ni++)
                    mma_tf32(c[mi][ni], a[mi][0], a[mi][1], a[mi][2], a[mi][3],
                             b[ni][0], b[ni][1]);
        }
    }

    // ---- finalize LayerNorm stats: reduce within 8-lane row groups ----
#pragma unroll
    for (int off = 4; off > 0; off >>= 1)
#pragma unroll
        for (int i = 0; i < 4; i++) {
            s1[i] += __shfl_xor_sync(0xffffffffu, s1[i], off);
            s2[i] += __shfl_xor_sync(0xffffffffu, s2[i], off);
        }
    if ((t & 7) == 0) {
#pragma unroll
        for (int i = 0; i < 4; i++) {
            float mu  = s1[i] * (1.f / FIN);
            float var = s2[i] * (1.f / FIN) - mu * mu;
            sstat[r0l + 32 * i] = make_float2(mu, rsqrtf(var + 1e-5f));
        }
    }
    if (is_attn && t < 128)
        *reinterpret_cast<float4*>(&slog[t][0]) = make_float4(0.f, 0.f, 0.f, 0.f);
    __syncthreads();

    // per-epilogue-row params: rows wm+g4+8q, q = 2*mi+hf
    float mu[4], rs[4];
    int   gi[4];
#pragma unroll
    for (int q = 0; q < 4; q++) {
        int rl = wm + g4 + 8 * q;
        float2 st = sstat[rl];
        mu[q] = st.x; rs[q] = st.y;
        gi[q] = bidx[m0 + rl];
    }

    if (!is_attn) {
#pragma unroll
        for (int mi = 0; mi < 2; mi++) {
#pragma unroll
            for (int ni = 0; ni < 4; ni++) {
                int n = n0 + wn + ni * 8 + 2 * t4;
                float2 u2  = *reinterpret_cast<const float2*>(&g_u[n]);
                float2 vb2 = *reinterpret_cast<const float2*>(&g_vb[n]);
#pragma unroll
                for (int hf = 0; hf < 2; hf++) {
                    int q = 2 * mi + hf;
                    float2 gg2 = *reinterpret_cast<const float2*>(&g_gg[gi[q] * NW + n]);
                    float o0 = rs[q] * (c[mi][ni][2 * hf]     - mu[q] * u2.x) + vb2.x + gg2.x;
                    float o1 = rs[q] * (c[mi][ni][2 * hf + 1] - mu[q] * u2.y) + vb2.y + gg2.y;
                    int rr = m0 + wm + mi * 16 + g4 + 8 * hf;
                    *reinterpret_cast<uint2*>(&g_h[(size_t)rr * H1D + n]) =
                        make_uint2(f2tf(silu_f(o0)), f2tf(silu_f(o1)));
                }
            }
        }
    } else {
        float pl[2][2][NH];
#pragma unroll
        for (int mi = 0; mi < 2; mi++)
#pragma unroll
            for (int hf = 0; hf < 2; hf++)
#pragma unroll
                for (int h = 0; h < NH; h++) pl[mi][hf][h] = 0.f;

#pragma unroll
        for (int mi = 0; mi < 2; mi++) {
#pragma unroll
            for (int ni = 0; ni < 4; ni++) {
                int nl = wn + ni * 8 + 2 * t4;        // attn-local col
                int n  = H1D + nl;                     // global weight col
                float2 u2  = *reinterpret_cast<const float2*>(&g_u[n]);
                float2 vb2 = *reinterpret_cast<const float2*>(&g_vb[n]);
                float4 a20 = *reinterpret_cast<const float4*>(&A2[nl * NH]);
                float4 a21 = *reinterpret_cast<const float4*>(&A2[(nl + 1) * NH]);
#pragma unroll
                for (int hf = 0; hf < 2; hf++) {
                    int q = 2 * mi + hf;
                    float2 gg2 = *reinterpret_cast<const float2*>(&g_gg[gi[q] * NW + n]);
                    float v0 = silu_f(rs[q] * (c[mi][ni][2 * hf]     - mu[q] * u2.x) + vb2.x + gg2.x);
                    float v1 = silu_f(rs[q] * (c[mi][ni][2 * hf + 1] - mu[q] * u2.y) + vb2.y + gg2.y);
                    pl[mi][hf][0] += v0 * a20.x + v1 * a21.x;
                    pl[mi][hf][1] += v0 * a20.y + v1 * a21.y;
                    pl[mi][hf][2] += v0 * a20.z + v1 * a21.z;
                    pl[mi][hf][3] += v0 * a20.w + v1 * a21.w;
                }
            }
        }
#pragma unroll
        for (int mi = 0; mi < 2; mi++)
#pragma unroll
            for (int hf = 0; hf < 2; hf++) {
                int rl = wm + mi * 16 + g4 + hf * 8;
#pragma unroll
                for (int h = 0; h < NH; h++)
                    atomicAdd(&slog[rl][h], pl[mi][hf][h]);
            }
        __syncthreads();

        if (t < 128) {
            int e = m0 + t;
            float4 l = *reinterpret_cast<float4*>(&slog[t][0]);
            float ae0 = __expf((l.x + ab2[0]) * 0.125f);
            float ae1 = __expf((l.y + ab2[1]) * 0.125f);
            float ae2 = __expf((l.z + ab2[2]) * 0.125f);
            float ae3 = __expf((l.w + ab2[3]) * 0.125f);
            *reinterpret_cast<float4*>(&g_ae[(size_t)e * NH]) = make_float4(ae0, ae1, ae2, ae3);
            int seg = bidx[e] * NNODE + ridx[e];
            atomicAdd(&g_den[seg * NH + 0], ae0);
            atomicAdd(&g_den[seg * NH + 1], ae1);
            atomicAdd(&g_den[seg * NH + 2], ae2);
            atomicAdd(&g_den[seg * NH + 3], ae3);
        }
    }
}

__global__ void invden_kernel()
{
    int i = blockIdx.x * blockDim.x + threadIdx.x;
    if (i < NSEG * NH) {
        float d = g_den[i];
        g_invden[i] = (d > 0.f) ? (1.f / d) : 0.f;
    }
}

// ================= GEMM2 + residual + fused attention-weighted pool =================
__global__ void __launch_bounds__(256) gemm2_fused(const float* __restrict__ b2,
                                                   const float* __restrict__ edges0,
                                                   const int* __restrict__ bidx,
                                                   const int* __restrict__ ridx,
                                                   float* __restrict__ Cout,
                                                   float* __restrict__ pooled)
{
    constexpr int LDA = H1D, KK = H1D, NTOT = OUTD;
    constexpr int SA = 36, SB = 72;
    __shared__ uint32_t As[128 * SA];
    __shared__ uint32_t Bs[32 * SB];

    const int t = threadIdx.x, lane = t & 31, wid = t >> 5;
    const int g4 = lane >> 2, t4 = lane & 3;
    const int wm = (wid & 3) * 32, wn = (wid >> 2) * 32;
    const int m0 = blockIdx.y * 128;

    float c[2][4][4];
#pragma unroll
    for (int mi = 0; mi < 2; mi++)
#pragma unroll
        for (int ni = 0; ni < 4; ni++)
#pragma unroll
            for (int q = 0; q < 4; q++) c[mi][ni][q] = 0.f;

    const uint32_t* Ap = g_h + (size_t)m0 * LDA;

    int arow[4], ac4[4];
#pragma unroll
    for (int i = 0; i < 4; i++) { int idx = t + 256 * i; arow[i] = idx >> 3; ac4[i] = idx & 7; }
    int brow[2], bc4[2];
#pragma unroll
    for (int i = 0; i < 2; i++) { int idx = t + 256 * i; brow[i] = idx >> 4; bc4[i] = idx & 15; }

    uint4 areg[4], breg[2];
#pragma unroll
    for (int i = 0; i < 4; i++)
        areg[i] = *reinterpret_cast<const uint4*>(&Ap[(size_t)arow[i] * LDA + ac4[i] * 4]);
#pragma unroll
    for (int i = 0; i < 2; i++)
        breg[i] = *reinterpret_cast<const uint4*>(&g_W2tf[(size_t)brow[i] * NTOT + bc4[i] * 4]);

#pragma unroll 1
    for (int k0 = 0; k0 < KK; k0 += 32) {
        __syncthreads();
#pragma unroll
        for (int i = 0; i < 4; i++)
            *reinterpret_cast<uint4*>(&As[arow[i] * SA + ac4[i] * 4]) = areg[i];
#pragma unroll
        for (int i = 0; i < 2; i++)
            *reinterpret_cast<uint4*>(&Bs[brow[i] * SB + bc4[i] * 4]) = breg[i];
        __syncthreads();

        if (k0 + 32 < KK) {
#pragma unroll
            for (int i = 0; i < 4; i++)
                areg[i] = *reinterpret_cast<const uint4*>(&Ap[(size_t)arow[i] * LDA + k0 + 32 + ac4[i] * 4]);
#pragma unroll
            for (int i = 0; i < 2; i++)
                breg[i] = *reinterpret_cast<const uint4*>(&g_W2tf[(size_t)(k0 + 32 + brow[i]) * NTOT + bc4[i] * 4]);
        }

#pragma unroll
        for (int ks = 0; ks < 4; ks++) {
            const int kk = ks * 8;
            uint32_t a[2][4], b[4][2];
#pragma unroll
            for (int mi = 0; mi < 2; mi++) {
                int mb = wm + mi * 16;
                a[mi][0] = As[(mb + g4) * SA + kk + t4];
                a[mi][1] = As[(mb + g4 + 8) * SA + kk + t4];
                a[mi][2] = As[(mb + g4) * SA + kk + t4 + 4];
                a[mi][3] = As[(mb + g4 + 8) * SA + kk + t4 + 4];
            }
#pragma unroll
            for (int ni = 0; ni < 4; ni++) {
                int nb = wn + ni * 8 + g4;
                b[ni][0] = Bs[(kk + t4) * SB + nb];
                b[ni][1] = Bs[(kk + t4 + 4) * SB + nb];
            }
#pragma unroll
            for (int mi = 0; mi < 2; mi++)
#pragma unroll
                for (int ni = 0; ni < 4; ni++)
                    mma_tf32(c[mi][ni], a[mi][0], a[mi][1], a[mi][2], a[mi][3],
                             b[ni][0], b[ni][1]);
        }
    }

    // per-row attention weights (4 rows per thread)
    int   segr[2][2];
    float aw[2][2][NH];
#pragma unroll
    for (int mi = 0; mi < 2; mi++)
#pragma unroll
        for (int hf = 0; hf < 2; hf++) {
            int r = m0 + wm + mi * 16 + g4 + hf * 8;
            int seg = bidx[r] * NNODE + ridx[r];
            segr[mi][hf] = seg;
            float4 ae4 = *reinterpret_cast<const float4*>(&g_ae[(size_t)r * NH]);
            float4 iv4 = *reinterpret_cast<const float4*>(&g_invden[(size_t)seg * NH]);
            aw[mi][hf][0] = ae4.x * iv4.x;
            aw[mi][hf][1] = ae4.y * iv4.y;
            aw[mi][hf][2] = ae4.z * iv4.z;
            aw[mi][hf][3] = ae4.w * iv4.w;
        }

#pragma unroll
    for (int mi = 0; mi < 2; mi++) {
#pragma unroll
        for (int ni = 0; ni < 4; ni++) {
            int n = wn + ni * 8 + 2 * t4;
            int h = n >> 4;
            float bv0 = b2[n], bv1 = b2[n + 1];
            int rr0 = m0 + wm + mi * 16 + g4;
            int rr1 = rr0 + 8;
            float2 e0 = *reinterpret_cast<const float2*>(&edges0[(size_t)rr0 * NTOT + n]);
            float2 e1 = *reinterpret_cast<const float2*>(&edges0[(size_t)rr1 * NTOT + n]);
            float o00 = c[mi][ni][0] + bv0 + e0.x;
            float o01 = c[mi][ni][1] + bv1 + e0.y;
            float o10 = c[mi][ni][2] + bv0 + e1.x;
            float o11 = c[mi][ni][3] + bv1 + e1.y;
            *reinterpret_cast<float2*>(&Cout[(size_t)rr0 * NTOT + n]) = make_float2(o00, o01);
            *reinterpret_cast<float2*>(&Cout[(size_t)rr1 * NTOT + n]) = make_float2(o10, o11);
            float w0 = aw[mi][0][h], w1 = aw[mi][1][h];
            atomicAdd(&pooled[(size_t)segr[mi][0] * OUTD + n],     o00 * w0);
            atomicAdd(&pooled[(size_t)segr[mi][0] * OUTD + n + 1], o01 * w0);
            atomicAdd(&pooled[(size_t)segr[mi][1] * OUTD + n],     o10 * w1);
            atomicAdd(&pooled[(size_t)segr[mi][1] * OUTD + n + 1], o11 * w1);
        }
    }
}

// ---------------- entry ----------------
extern "C" void kernel_launch(void* const* d_in, const int* in_sizes, int n_in,
                              void* d_out, int out_size)
{
    const float* nodes  = (const float*)d_in[0];
    const float* edges0 = (const float*)d_in[1];
    const float* globs  = (const float*)d_in[2];
    const float* ln_g   = (const float*)d_in[3];
    const float* ln_b   = (const float*)d_in[4];
    const float* W1     = (const float*)d_in[5];
    const float* b1     = (const float*)d_in[6];
    const float* W2     = (const float*)d_in[7];
    const float* b2     = (const float*)d_in[8];
    const float* A1     = (const float*)d_in[9];
    const float* ab1    = (const float*)d_in[10];
    const float* A2     = (const float*)d_in[11];
    const float* ab2    = (const float*)d_in[12];
    const int*   bidx   = (const int*)d_in[13];
    const int*   sidx   = (const int*)d_in[14];
    const int*   ridx   = (const int*)d_in[15];

    float* out    = (float*)d_out;
    float* newe   = out;
    float* pooled = out + (size_t)EDG * OUTD;

    prep_kernel<<<(NSEG * OUTD + 255) / 256, 256>>>(W1, A1, W2, ln_g, pooled);
    prep2_kernel<<<1, NW>>>(W1, A1, b1, ab1, ln_g, ln_b, globs);
    gemm1_fused<<<dim3(5, EDG / 128), 256>>>(nodes, edges0, bidx, sidx, ridx, A2, ab2);
    invden_kernel<<<(NSEG * NH + 255) / 256, 256>>>();
    gemm2_fused<<<dim3(1, EDG / 128), 256>>>(b2, edges0, bidx, ridx, newe, pooled);
}

// round 10
// speedup vs baseline: 2.6479x; 1.0444x over previous
#include <cuda_runtime.h>
#include <math.h>
#include <stdint.h>

// ---------------- problem constants ----------------
#define EDG   262144
#define BGR   8
#define NNODE 512
#define NDIM  128
#define EDIM  64
#define GDIM  32
#define FIN   320
#define H1D   256
#define AHD   64
#define KW    320            // GEMM1 K after LN-fold
#define NW    320            // GEMM1 N (H1D + AHD)
#define OUTD  64
#define NH    4
#define NSEG  (BGR*NNODE)

#define SA    36             // padded A row stride (floats)
#define SB    72             // padded B row stride (floats)
#define NSTAGE 3
#define ASTRIDE (128*SA)     // u32 per A stage
#define BSTRIDE (32*SB)      // u32 per B stage
#define DYN_SMEM ((NSTAGE*(ASTRIDE+BSTRIDE))*4)

// ---------------- device scratch ----------------
__device__ uint32_t g_h[(size_t)EDG * H1D];    // silu hidden as tf32 bits
__device__ uint32_t g_Wtf[KW * NW];            // ln_g-scaled [W1|A1], tf32 bits
__device__ uint32_t g_W2tf[H1D * OUTD];        // W2, tf32 bits
__device__ float    g_u[NW];
__device__ float    g_vb[NW];
__device__ float    g_gg[BGR * NW];
__device__ float    g_ae[EDG * NH];
__device__ float    g_den[NSEG * NH];
__device__ float    g_invden[NSEG * NH];

// ---------------- helpers ----------------
__device__ __forceinline__ uint32_t f2tf(float f) {
    uint32_t r;
    asm("cvt.rna.tf32.f32 %0, %1;" : "=r"(r) : "f"(f));
    return r;
}
__device__ __forceinline__ void mma_tf32(float c[4],
                                         uint32_t a0, uint32_t a1, uint32_t a2, uint32_t a3,
                                         uint32_t b0, uint32_t b1)
{
    asm volatile(
        "mma.sync.aligned.m16n8k8.row.col.f32.tf32.tf32.f32 "
        "{%0,%1,%2,%3}, {%4,%5,%6,%7}, {%8,%9}, {%0,%1,%2,%3};"
        : "+f"(c[0]), "+f"(c[1]), "+f"(c[2]), "+f"(c[3])
        : "r"(a0), "r"(a1), "r"(a2), "r"(a3), "r"(b0), "r"(b1));
}
__device__ __forceinline__ float silu_f(float v) { return v / (1.f + __expf(-v)); }

#define CP16(dst_u32, src_ptr) \
    asm volatile("cp.async.cg.shared.global [%0], [%1], 16;" :: "r"(dst_u32), "l"(src_ptr))
#define CP_COMMIT() asm volatile("cp.async.commit_group;" ::: "memory")
#define CP_WAIT1()  asm volatile("cp.async.wait_group 1;" ::: "memory")

__device__ __forceinline__ float wcat(const float* W1, const float* A1, int k, int n) {
    return (n < H1D) ? W1[k * H1D + n] : A1[k * AHD + (n - H1D)];
}

// ---------------- prep ----------------
__global__ void prep_kernel(const float* __restrict__ W1, const float* __restrict__ A1,
                            const float* __restrict__ W2, const float* __restrict__ ln_g,
                            float* __restrict__ pooled)
{
    int i = blockIdx.x * blockDim.x + threadIdx.x;
    if (i < KW * NW) {
        int k = i / NW, n = i % NW;
        g_Wtf[i] = f2tf(ln_g[k] * wcat(W1, A1, k, n));
    }
    if (i < H1D * OUTD) g_W2tf[i] = f2tf(W2[i]);
    if (i < NSEG * NH) g_den[i] = 0.f;
    if (i < NSEG * OUTD) pooled[i] = 0.f;
}

__global__ void prep2_kernel(const float* __restrict__ W1, const float* __restrict__ A1,
                             const float* __restrict__ b1, const float* __restrict__ ab1,
                             const float* __restrict__ ln_g, const float* __restrict__ ln_b,
                             const float* __restrict__ globs)
{
    int n = threadIdx.x;
    if (n >= NW) return;
    float u = 0.f, vb = 0.f;
    for (int k = 0; k < KW; k++) {
        float w = wcat(W1, A1, k, n);
        u  += ln_g[k] * w;
        vb += ln_b[k] * w;
    }
    vb += (n < H1D) ? b1[n] : ab1[n - H1D];
    g_u[n] = u;
    g_vb[n] = vb;
    for (int b = 0; b < BGR; b++) {
        float s = 0.f;
        for (int j = 0; j < GDIM; j++)
            s += globs[b * GDIM + j] * wcat(W1, A1, KW + j, n);
        g_gg[b * NW + n] = s;
    }
}

// ================= fused gather + GEMM1, cp.async 3-stage pipeline =================
__global__ void __launch_bounds__(256) gemm1_fused(const float* __restrict__ nodes,
                                                   const float* __restrict__ edges0,
                                                   const int* __restrict__ bidx,
                                                   const int* __restrict__ sidx,
                                                   const int* __restrict__ ridx,
                                                   const float* __restrict__ A2,
                                                   const float* __restrict__ ab2)
{
    extern __shared__ uint32_t dyn[];
    uint32_t* As = dyn;                         // NSTAGE * ASTRIDE
    uint32_t* Bs = dyn + NSTAGE * ASTRIDE;      // NSTAGE * BSTRIDE
    __shared__ float2 sstat[128];
    __shared__ float  slog[128][NH];

    const int t = threadIdx.x, lane = t & 31, wid = t >> 5;
    const int g4 = lane >> 2, t4 = lane & 3;
    const int wm = (wid & 3) * 32, wn = (wid >> 2) * 32;
    const int m0 = blockIdx.y * 128, n0 = blockIdx.x * 64;
    const bool is_attn = (blockIdx.x == 4);

    float c[2][4][4];
#pragma unroll
    for (int mi = 0; mi < 2; mi++)
#pragma unroll
        for (int ni = 0; ni < 4; ni++)
#pragma unroll
            for (int q = 0; q < 4; q++) c[mi][ni][q] = 0.f;

    // per-thread staging geometry
    const int ac4 = t & 7;       // 16B chunk col within 32-wide k stage
    const int r0l = t >> 3;      // local row base 0..31 (rows r0l+32i)
    int soff[4], roff[4];
#pragma unroll
    for (int i = 0; i < 4; i++) {
        int e = m0 + r0l + 32 * i;
        int b = bidx[e];
        soff[i] = (b * NNODE + sidx[e]) * NDIM;
        roff[i] = (b * NNODE + ridx[e]) * NDIM;
    }
    int brow[2], bc4[2];
#pragma unroll
    for (int i = 0; i < 2; i++) { int idx = t + 256 * i; brow[i] = idx >> 4; bc4[i] = idx & 15; }

    // smem byte addresses for this thread's staging slots
    uint32_t aslot[4], bslot[2];
#pragma unroll
    for (int i = 0; i < 4; i++)
        aslot[i] = (uint32_t)__cvta_generic_to_shared(&As[(r0l + 32 * i) * SA + ac4 * 4]);
#pragma unroll
    for (int i = 0; i < 2; i++)
        bslot[i] = (uint32_t)__cvta_generic_to_shared(&Bs[brow[i] * SB + bc4[i] * 4]);

    // issue one stage's cp.asyncs into buffer `buf`
    auto issue = [&](int k0, int buf) {
        int kq = k0 + ac4 * 4;
        uint32_t ab = buf * (ASTRIDE * 4);
        uint32_t bb = buf * (BSTRIDE * 4);
        if (k0 < 64) {
#pragma unroll
            for (int i = 0; i < 4; i++)
                CP16(aslot[i] + ab, edges0 + (size_t)(m0 + r0l + 32 * i) * EDIM + kq);
        } else if (k0 < 192) {
#pragma unroll
            for (int i = 0; i < 4; i++)
                CP16(aslot[i] + ab, nodes + soff[i] + (kq - 64));
        } else {
#pragma unroll
            for (int i = 0; i < 4; i++)
                CP16(aslot[i] + ab, nodes + roff[i] + (kq - 192));
        }
#pragma unroll
        for (int i = 0; i < 2; i++)
            CP16(bslot[i] + bb, &g_Wtf[(size_t)(k0 + brow[i]) * NW + n0 + bc4[i] * 4]);
    };

    float s1[4] = {0.f, 0.f, 0.f, 0.f}, s2[4] = {0.f, 0.f, 0.f, 0.f};

    issue(0, 0);  CP_COMMIT();
    issue(32, 1); CP_COMMIT();

    constexpr int NIT = KW / 32;   // 10
#pragma unroll 1
    for (int it = 0; it < NIT; it++) {
        CP_WAIT1();
        __syncthreads();
        const int buf = it % NSTAGE;
        const uint32_t* Ab = As + buf * ASTRIDE;
        const uint32_t* Bb = Bs + buf * BSTRIDE;

        // LayerNorm stats readback (raw fp32 bits just landed)
#pragma unroll
        for (int i = 0; i < 4; i++) {
            float4 a = *reinterpret_cast<const float4*>(&Ab[(r0l + 32 * i) * SA + ac4 * 4]);
            s1[i] += a.x + a.y + a.z + a.w;
            s2[i] += a.x * a.x + a.y * a.y + a.z * a.z + a.w * a.w;
        }

        // prefetch next+1 stage
        if (it + 2 < NIT) issue((it + 2) * 32, (it + 2) % NSTAGE);
        CP_COMMIT();

        // mma on current stage
#pragma unroll
        for (int ks = 0; ks < 4; ks++) {
            const int kk = ks * 8;
            uint32_t a[2][4], b[4][2];
#pragma unroll
            for (int mi = 0; mi < 2; mi++) {
                int mb = wm + mi * 16;
                a[mi][0] = Ab[(mb + g4) * SA + kk + t4];
                a[mi][1] = Ab[(mb + g4 + 8) * SA + kk + t4];
                a[mi][2] = Ab[(mb + g4) * SA + kk + t4 + 4];
                a[mi][3] = Ab[(mb + g4 + 8) * SA + kk + t4 + 4];
            }
#pragma unroll
            for (int ni = 0; ni < 4; ni++) {
                int nb = wn + ni * 8 + g4;
                b[ni][0] = Bb[(kk + t4) * SB + nb];
                b[ni][1] = Bb[(kk + t4 + 4) * SB + nb];
            }
#pragma unroll
            for (int mi = 0; mi < 2; mi++)
#pragma unroll
                for (int ni = 0; ni < 4; ni++)
                    mma_tf32(c[mi][ni], a[mi][0], a[mi][1], a[mi][2], a[mi][3],
                             b[ni][0], b[ni][1]);
        }
    }

    // ---- finalize LN stats: reduce across the 8 threads of each row ----
#pragma unroll
    for (int off = 4; off > 0; off >>= 1)
#pragma unroll
        for (int i = 0; i < 4; i++) {
            s1[i] += __shfl_xor_sync(0xffffffffu, s1[i], off);
            s2[i] += __shfl_xor_sync(0xffffffffu, s2[i], off);
        }
    if ((t & 7) == 0) {
#pragma unroll
        for (int i = 0; i < 4; i++) {
            float mu  = s1[i] * (1.f / FIN);
            float var = s2[i] * (1.f / FIN) - mu * mu;
            sstat[r0l + 32 * i] = make_float2(mu, rsqrtf(var + 1e-5f));
        }
    }
    if (is_attn && t < 128)
        *reinterpret_cast<float4*>(&slog[t][0]) = make_float4(0.f, 0.f, 0.f, 0.f);
    __syncthreads();

    float mu[4], rs[4];
    int   gi[4];
#pragma unroll
    for (int q = 0; q < 4; q++) {
        int rl = wm + g4 + 8 * q;
        float2 st = sstat[rl];
        mu[q] = st.x; rs[q] = st.y;
        gi[q] = bidx[m0 + rl];
    }

    if (!is_attn) {
#pragma unroll
        for (int mi = 0; mi < 2; mi++) {
#pragma unroll
            for (int ni = 0; ni < 4; ni++) {
                int n = n0 + wn + ni * 8 + 2 * t4;
                float2 u2  = *reinterpret_cast<const float2*>(&g_u[n]);
                float2 vb2 = *reinterpret_cast<const float2*>(&g_vb[n]);
#pragma unroll
                for (int hf = 0; hf < 2; hf++) {
                    int q = 2 * mi + hf;
                    float2 gg2 = *reinterpret_cast<const float2*>(&g_gg[gi[q] * NW + n]);
                    float o0 = rs[q] * (c[mi][ni][2 * hf]     - mu[q] * u2.x) + vb2.x + gg2.x;
                    float o1 = rs[q] * (c[mi][ni][2 * hf + 1] - mu[q] * u2.y) + vb2.y + gg2.y;
                    int rr = m0 + wm + mi * 16 + g4 + 8 * hf;
                    *reinterpret_cast<uint2*>(&g_h[(size_t)rr * H1D + n]) =
                        make_uint2(f2tf(silu_f(o0)), f2tf(silu_f(o1)));
                }
            }
        }
    } else {
        float pl[2][2][NH];
#pragma unroll
        for (int mi = 0; mi < 2; mi++)
#pragma unroll
            for (int hf = 0; hf < 2; hf++)
#pragma unroll
                for (int h = 0; h < NH; h++) pl[mi][hf][h] = 0.f;

#pragma unroll
        for (int mi = 0; mi < 2; mi++) {
#pragma unroll
            for (int ni = 0; ni < 4; ni++) {
                int nl = wn + ni * 8 + 2 * t4;
                int n  = H1D + nl;
                float2 u2  = *reinterpret_cast<const float2*>(&g_u[n]);
                float2 vb2 = *reinterpret_cast<const float2*>(&g_vb[n]);
                float4 a20 = *reinterpret_cast<const float4*>(&A2[nl * NH]);
                float4 a21 = *reinterpret_cast<const float4*>(&A2[(nl + 1) * NH]);
#pragma unroll
                for (int hf = 0; hf < 2; hf++) {
                    int q = 2 * mi + hf;
                    float2 gg2 = *reinterpret_cast<const float2*>(&g_gg[gi[q] * NW + n]);
                    float v0 = silu_f(rs[q] * (c[mi][ni][2 * hf]     - mu[q] * u2.x) + vb2.x + gg2.x);
                    float v1 = silu_f(rs[q] * (c[mi][ni][2 * hf + 1] - mu[q] * u2.y) + vb2.y + gg2.y);
                    pl[mi][hf][0] += v0 * a20.x + v1 * a21.x;
                    pl[mi][hf][1] += v0 * a20.y + v1 * a21.y;
                    pl[mi][hf][2] += v0 * a20.z + v1 * a21.z;
                    pl[mi][hf][3] += v0 * a20.w + v1 * a21.w;
                }
            }
        }
#pragma unroll
        for (int mi = 0; mi < 2; mi++)
#pragma unroll
            for (int hf = 0; hf < 2; hf++) {
                int rl = wm + mi * 16 + g4 + hf * 8;
#pragma unroll
                for (int h = 0; h < NH; h++)
                    atomicAdd(&slog[rl][h], pl[mi][hf][h]);
            }
        __syncthreads();

        if (t < 128) {
            int e = m0 + t;
            float4 l = *reinterpret_cast<float4*>(&slog[t][0]);
            float ae0 = __expf((l.x + ab2[0]) * 0.125f);
            float ae1 = __expf((l.y + ab2[1]) * 0.125f);
            float ae2 = __expf((l.z + ab2[2]) * 0.125f);
            float ae3 = __expf((l.w + ab2[3]) * 0.125f);
            *reinterpret_cast<float4*>(&g_ae[(size_t)e * NH]) = make_float4(ae0, ae1, ae2, ae3);
            int seg = bidx[e] * NNODE + ridx[e];
            atomicAdd(&g_den[seg * NH + 0], ae0);
            atomicAdd(&g_den[seg * NH + 1], ae1);
            atomicAdd(&g_den[seg * NH + 2], ae2);
            atomicAdd(&g_den[seg * NH + 3], ae3);
        }
    }
}

__global__ void invden_kernel()
{
    int i = blockIdx.x * blockDim.x + threadIdx.x;
    if (i < NSEG * NH) {
        float d = g_den[i];
        g_invden[i] = (d > 0.f) ? (1.f / d) : 0.f;
    }
}

// ================= GEMM2 + residual + pool, cp.async 3-stage pipeline =================
__global__ void __launch_bounds__(256) gemm2_fused(const float* __restrict__ b2,
                                                   const float* __restrict__ edges0,
                                                   const int* __restrict__ bidx,
                                                   const int* __restrict__ ridx,
                                                   float* __restrict__ Cout,
                                                   float* __restrict__ pooled)
{
    extern __shared__ uint32_t dyn[];
    uint32_t* As = dyn;
    uint32_t* Bs = dyn + NSTAGE * ASTRIDE;

    constexpr int LDA = H1D, NTOT = OUTD;
    const int t = threadIdx.x, lane = t & 31, wid = t >> 5;
    const int g4 = lane >> 2, t4 = lane & 3;
    const int wm = (wid & 3) * 32, wn = (wid >> 2) * 32;
    const int m0 = blockIdx.y * 128;

    float c[2][4][4];
#pragma unroll
    for (int mi = 0; mi < 2; mi++)
#pragma unroll
        for (int ni = 0; ni < 4; ni++)
#pragma unroll
            for (int q = 0; q < 4; q++) c[mi][ni][q] = 0.f;

    const uint32_t* Ap = g_h + (size_t)m0 * LDA;

    int arow[4], ac4[4];
#pragma unroll
    for (int i = 0; i < 4; i++) { int idx = t + 256 * i; arow[i] = idx >> 3; ac4[i] = idx & 7; }
    int brow[2], bc4[2];
#pragma unroll
    for (int i = 0; i < 2; i++) { int idx = t + 256 * i; brow[i] = idx >> 4; bc4[i] = idx & 15; }

    uint32_t aslot[4], bslot[2];
#pragma unroll
    for (int i = 0; i < 4; i++)
        aslot[i] = (uint32_t)__cvta_generic_to_shared(&As[arow[i] * SA + ac4[i] * 4]);
#pragma unroll
    for (int i = 0; i < 2; i++)
        bslot[i] = (uint32_t)__cvta_generic_to_shared(&Bs[brow[i] * SB + bc4[i] * 4]);

    auto issue = [&](int k0, int buf) {
        uint32_t ab = buf * (ASTRIDE * 4);
        uint32_t bb = buf * (BSTRIDE * 4);
#pragma unroll
        for (int i = 0; i < 4; i++)
            CP16(aslot[i] + ab, Ap + (size_t)arow[i] * LDA + k0 + ac4[i] * 4);
#pragma unroll
        for (int i = 0; i < 2; i++)
            CP16(bslot[i] + bb, &g_W2tf[(size_t)(k0 + brow[i]) * NTOT + bc4[i] * 4]);
    };

    issue(0, 0);  CP_COMMIT();
    issue(32, 1); CP_COMMIT();

    constexpr int NIT = H1D / 32;   // 8
#pragma unroll 1
    for (int it = 0; it < NIT; it++) {
        CP_WAIT1();
        __syncthreads();
        const int buf = it % NSTAGE;
        const uint32_t* Ab = As + buf * ASTRIDE;
        const uint32_t* Bb = Bs + buf * BSTRIDE;

        if (it + 2 < NIT) issue((it + 2) * 32, (it + 2) % NSTAGE);
        CP_COMMIT();

#pragma unroll
        for (int ks = 0; ks < 4; ks++) {
            const int kk = ks * 8;
            uint32_t a[2][4], b[4][2];
#pragma unroll
            for (int mi = 0; mi < 2; mi++) {
                int mb = wm + mi * 16;
                a[mi][0] = Ab[(mb + g4) * SA + kk + t4];
                a[mi][1] = Ab[(mb + g4 + 8) * SA + kk + t4];
                a[mi][2] = Ab[(mb + g4) * SA + kk + t4 + 4];
                a[mi][3] = Ab[(mb + g4 + 8) * SA + kk + t4 + 4];
            }
#pragma unroll
            for (int ni = 0; ni < 4; ni++) {
                int nb = wn + ni * 8 + g4;
                b[ni][0] = Bb[(kk + t4) * SB + nb];
                b[ni][1] = Bb[(kk + t4 + 4) * SB + nb];
            }
#pragma unroll
            for (int mi = 0; mi < 2; mi++)
#pragma unroll
                for (int ni = 0; ni < 4; ni++)
                    mma_tf32(c[mi][ni], a[mi][0], a[mi][1], a[mi][2], a[mi][3],
                             b[ni][0], b[ni][1]);
        }
    }

    // per-row attention weights
    int   segr[2][2];
    float aw[2][2][NH];
#pragma unroll
    for (int mi = 0; mi < 2; mi++)
#pragma unroll
        for (int hf = 0; hf < 2; hf++) {
            int r = m0 + wm + mi * 16 + g4 + hf * 8;
            int seg = bidx[r] * NNODE + ridx[r];
            segr[mi][hf] = seg;
            float4 ae4 = *reinterpret_cast<const float4*>(&g_ae[(size_t)r * NH]);
            float4 iv4 = *reinterpret_cast<const float4*>(&g_invden[(size_t)seg * NH]);
            aw[mi][hf][0] = ae4.x * iv4.x;
            aw[mi][hf][1] = ae4.y * iv4.y;
            aw[mi][hf][2] = ae4.z * iv4.z;
            aw[mi][hf][3] = ae4.w * iv4.w;
        }

#pragma unroll
    for (int mi = 0; mi < 2; mi++) {
#pragma unroll
        for (int ni = 0; ni < 4; ni++) {
            int n = wn + ni * 8 + 2 * t4;
            int h = n >> 4;
            float bv0 = b2[n], bv1 = b2[n + 1];
            int rr0 = m0 + wm + mi * 16 + g4;
            int rr1 = rr0 + 8;
            float2 e0 = *reinterpret_cast<const float2*>(&edges0[(size_t)rr0 * NTOT + n]);
            float2 e1 = *reinterpret_cast<const float2*>(&edges0[(size_t)rr1 * NTOT + n]);
            float o00 = c[mi][ni][0] + bv0 + e0.x;
            float o01 = c[mi][ni][1] + bv1 + e0.y;
            float o10 = c[mi][ni][2] + bv0 + e1.x;
            float o11 = c[mi][ni][3] + bv1 + e1.y;
            *reinterpret_cast<float2*>(&Cout[(size_t)rr0 * NTOT + n]) = make_float2(o00, o01);
            *reinterpret_cast<float2*>(&Cout[(size_t)rr1 * NTOT + n]) = make_float2(o10, o11);
            float w0 = aw[mi][0][h], w1 = aw[mi][1][h];
            atomicAdd(&pooled[(size_t)segr[mi][0] * OUTD + n],     o00 * w0);
            atomicAdd(&pooled[(size_t)segr[mi][0] * OUTD + n + 1], o01 * w0);
            atomicAdd(&pooled[(size_t)segr[mi][1] * OUTD + n],     o10 * w1);
            atomicAdd(&pooled[(size_t)segr[mi][1] * OUTD + n + 1], o11 * w1);
        }
    }
}

// ---------------- entry ----------------
extern "C" void kernel_launch(void* const* d_in, const int* in_sizes, int n_in,
                              void* d_out, int out_size)
{
    const float* nodes  = (const float*)d_in[0];
    const float* edges0 = (const float*)d_in[1];
    const float* globs  = (const float*)d_in[2];
    const float* ln_g   = (const float*)d_in[3];
    const float* ln_b   = (const float*)d_in[4];
    const float* W1     = (const float*)d_in[5];
    const float* b1     = (const float*)d_in[6];
    const float* W2     = (const float*)d_in[7];
    const float* b2     = (const float*)d_in[8];
    const float* A1     = (const float*)d_in[9];
    const float* ab1    = (const float*)d_in[10];
    const float* A2     = (const float*)d_in[11];
    const float* ab2    = (const float*)d_in[12];
    const int*   bidx   = (const int*)d_in[13];
    const int*   sidx   = (const int*)d_in[14];
    const int*   ridx   = (const int*)d_in[15];

    float* out    = (float*)d_out;
    float* newe   = out;
    float* pooled = out + (size_t)EDG * OUTD;

    static bool attr_done = false;
    if (!attr_done) {   // idempotent device attribute; not a memory op, not captured
        cudaFuncSetAttribute(gemm1_fused, cudaFuncAttributeMaxDynamicSharedMemorySize, DYN_SMEM);
        cudaFuncSetAttribute(gemm2_fused, cudaFuncAttributeMaxDynamicSharedMemorySize, DYN_SMEM);
        attr_done = true;
    }

    prep_kernel<<<(NSEG * OUTD + 255) / 256, 256>>>(W1, A1, W2, ln_g, pooled);
    prep2_kernel<<<1, NW>>>(W1, A1, b1, ab1, ln_g, ln_b, globs);
    gemm1_fused<<<dim3(5, EDG / 128), 256, DYN_SMEM>>>(nodes, edges0, bidx, sidx, ridx, A2, ab2);
    invden_kernel<<<(NSEG * NH + 255) / 256, 256>>>();
    gemm2_fused<<<dim3(1, EDG / 128), 256, DYN_SMEM>>>(b2, edges0, bidx, ridx, newe, pooled);
}

// round 12
// speedup vs baseline: 2.8377x; 1.0717x over previous
#include <cuda_runtime.h>
#include <math.h>
#include <stdint.h>

// ---------------- problem constants ----------------
#define EDG   262144
#define BGR   8
#define NNODE 512
#define NDIM  128
#define EDIM  64
#define GDIM  32
#define FIN   320
#define H1D   256
#define AHD   64
#define KW    320            // GEMM1 K after LN-fold
#define NW    320            // GEMM1 N (H1D + AHD)
#define OUTD  64
#define NH    4
#define NSEG  (BGR*NNODE)

#define SA    36             // padded A row stride (u32)
#define SB    72             // padded B row stride (u32)
#define NSTAGE 2
#define ASTRIDE (128*SA)     // u32 per A stage
#define BSTRIDE (32*SB)      // u32 per B stage
#define DYN_SMEM ((NSTAGE*(ASTRIDE+BSTRIDE))*4)   // 55296 B

// ---------------- device scratch ----------------
__device__ uint32_t g_h[(size_t)EDG * H1D];    // silu hidden as tf32 bits
__device__ uint32_t g_Wtf[KW * NW];            // ln_g-scaled [W1|A1], tf32 bits
__device__ uint32_t g_W2tf[H1D * OUTD];        // W2, tf32 bits
__device__ float    g_u[NW];
__device__ float    g_vb[NW];
__device__ float    g_gg[BGR * NW];
__device__ float    g_ae[EDG * NH];
__device__ float    g_den[NSEG * NH];
__device__ float    g_invden[NSEG * NH];

// ---------------- helpers ----------------
__device__ __forceinline__ uint32_t f2tf(float f) {
    uint32_t r;
    asm("cvt.rna.tf32.f32 %0, %1;" : "=r"(r) : "f"(f));
    return r;
}
__device__ __forceinline__ void mma_tf32(float c[4],
                                         uint32_t a0, uint32_t a1, uint32_t a2, uint32_t a3,
                                         uint32_t b0, uint32_t b1)
{
    asm volatile(
        "mma.sync.aligned.m16n8k8.row.col.f32.tf32.tf32.f32 "
        "{%0,%1,%2,%3}, {%4,%5,%6,%7}, {%8,%9}, {%0,%1,%2,%3};"
        : "+f"(c[0]), "+f"(c[1]), "+f"(c[2]), "+f"(c[3])
        : "r"(a0), "r"(a1), "r"(a2), "r"(a3), "r"(b0), "r"(b1));
}
__device__ __forceinline__ float silu_f(float v) { return v / (1.f + __expf(-v)); }

#define CP16(dst_u32, src_ptr) \
    asm volatile("cp.async.cg.shared.global [%0], [%1], 16;" :: "r"(dst_u32), "l"(src_ptr))
#define CP_COMMIT() asm volatile("cp.async.commit_group;" ::: "memory")
#define CP_WAIT0()  asm volatile("cp.async.wait_group 0;" ::: "memory")

__device__ __forceinline__ float wcat(const float* W1, const float* A1, int k, int n) {
    return (n < H1D) ? W1[k * H1D + n] : A1[k * AHD + (n - H1D)];
}

// ---------------- prep ----------------
__global__ void prep_kernel(const float* __restrict__ W1, const float* __restrict__ A1,
                            const float* __restrict__ W2, const float* __restrict__ ln_g,
                            float* __restrict__ pooled)
{
    int i = blockIdx.x * blockDim.x + threadIdx.x;
    if (i < KW * NW) {
        int k = i / NW, n = i % NW;
        g_Wtf[i] = f2tf(ln_g[k] * wcat(W1, A1, k, n));
    }
    if (i < H1D * OUTD) g_W2tf[i] = f2tf(W2[i]);
    if (i < NSEG * NH) g_den[i] = 0.f;
    if (i < NSEG * OUTD) pooled[i] = 0.f;
}

__global__ void prep2_kernel(const float* __restrict__ W1, const float* __restrict__ A1,
                             const float* __restrict__ b1, const float* __restrict__ ab1,
                             const float* __restrict__ ln_g, const float* __restrict__ ln_b,
                             const float* __restrict__ globs)
{
    int n = threadIdx.x;
    if (n >= NW) return;
    float u = 0.f, vb = 0.f;
    for (int k = 0; k < KW; k++) {
        float w = wcat(W1, A1, k, n);
        u  += ln_g[k] * w;
        vb += ln_b[k] * w;
    }
    vb += (n < H1D) ? b1[n] : ab1[n - H1D];
    g_u[n] = u;
    g_vb[n] = vb;
    for (int b = 0; b < BGR; b++) {
        float s = 0.f;
        for (int j = 0; j < GDIM; j++)
            s += globs[b * GDIM + j] * wcat(W1, A1, KW + j, n);
        g_gg[b * NW + n] = s;
    }
}

// ================= fused gather + GEMM1, 2-stage cp.async, 3 CTAs/SM =================
__global__ void __launch_bounds__(256, 3) gemm1_fused(const float* __restrict__ nodes,
                                                      const float* __restrict__ edges0,
                                                      const int* __restrict__ bidx,
                                                      const int* __restrict__ sidx,
                                                      const int* __restrict__ ridx,
                                                      const float* __restrict__ A2,
                                                      const float* __restrict__ ab2)
{
    extern __shared__ uint32_t dyn[];
    uint32_t* As = dyn;                         // NSTAGE * ASTRIDE
    uint32_t* Bs = dyn + NSTAGE * ASTRIDE;      // NSTAGE * BSTRIDE
    __shared__ float2 sstat[128];
    __shared__ float  slog[128][NH];

    const int t = threadIdx.x, lane = t & 31, wid = t >> 5;
    const int g4 = lane >> 2, t4 = lane & 3;
    const int wm = (wid & 3) * 32, wn = (wid >> 2) * 32;
    const int m0 = blockIdx.y * 128, n0 = blockIdx.x * 64;
    const bool is_attn = (blockIdx.x == 4);

    float c[2][4][4];
#pragma unroll
    for (int mi = 0; mi < 2; mi++)
#pragma unroll
        for (int ni = 0; ni < 4; ni++)
#pragma unroll
            for (int q = 0; q < 4; q++) c[mi][ni][q] = 0.f;

    // staging geometry: 8 threads per row, rows r0l+32i
    const int ac4 = t & 7;
    const int r0l = t >> 3;
    int soff[4], roff[4];
#pragma unroll
    for (int i = 0; i < 4; i++) {
        int e = m0 + r0l + 32 * i;
        int b = bidx[e];
        soff[i] = (b * NNODE + sidx[e]) * NDIM;
        roff[i] = (b * NNODE + ridx[e]) * NDIM;
    }
    int brow[2], bc4[2];
#pragma unroll
    for (int i = 0; i < 2; i++) { int idx = t + 256 * i; brow[i] = idx >> 4; bc4[i] = idx & 15; }

    uint32_t aslot[4], bslot[2];
#pragma unroll
    for (int i = 0; i < 4; i++)
        aslot[i] = (uint32_t)__cvta_generic_to_shared(&As[(r0l + 32 * i) * SA + ac4 * 4]);
#pragma unroll
    for (int i = 0; i < 2; i++)
        bslot[i] = (uint32_t)__cvta_generic_to_shared(&Bs[brow[i] * SB + bc4[i] * 4]);

    auto issue = [&](int it) {
        int k0 = it * 32;
        uint32_t ab = (it & 1) * (ASTRIDE * 4);
        uint32_t bb = (it & 1) * (BSTRIDE * 4);
        int kq = k0 + ac4 * 4;
        if (k0 < 64) {
#pragma unroll
            for (int i = 0; i < 4; i++)
                CP16(aslot[i] + ab, edges0 + (size_t)(m0 + r0l + 32 * i) * EDIM + kq);
        } else if (k0 < 192) {
#pragma unroll
            for (int i = 0; i < 4; i++)
                CP16(aslot[i] + ab, nodes + soff[i] + (kq - 64));
        } else {
#pragma unroll
            for (int i = 0; i < 4; i++)
                CP16(aslot[i] + ab, nodes + roff[i] + (kq - 192));
        }
#pragma unroll
        for (int i = 0; i < 2; i++)
            CP16(bslot[i] + bb, &g_Wtf[(size_t)(k0 + brow[i]) * NW + n0 + bc4[i] * 4]);
    };

    float s1[4] = {0.f, 0.f, 0.f, 0.f}, s2[4] = {0.f, 0.f, 0.f, 0.f};

    issue(0); CP_COMMIT();

    constexpr int NIT = KW / 32;   // 10
#pragma unroll 1
    for (int it = 0; it < NIT; it++) {
        CP_WAIT0();
        __syncthreads();
        // prefetch next stage while computing this one (buffer it+1 is free:
        // its last readers finished compute(it-1) before this barrier)
        if (it + 1 < NIT) { issue(it + 1); CP_COMMIT(); }

        const int buf = it & 1;
        const uint32_t* Ab = As + buf * ASTRIDE;
        const uint32_t* Bb = Bs + buf * BSTRIDE;

        // LayerNorm stats readback (raw fp32 bits just landed)
#pragma unroll
        for (int i = 0; i < 4; i++) {
            float4 a = *reinterpret_cast<const float4*>(&Ab[(r0l + 32 * i) * SA + ac4 * 4]);
            s1[i] += a.x + a.y + a.z + a.w;
            s2[i] += a.x * a.x + a.y * a.y + a.z * a.z + a.w * a.w;
        }

#pragma unroll
        for (int ks = 0; ks < 4; ks++) {
            const int kk = ks * 8;
            uint32_t a[2][4], b[4][2];
#pragma unroll
            for (int mi = 0; mi < 2; mi++) {
                int mb = wm + mi * 16;
                a[mi][0] = Ab[(mb + g4) * SA + kk + t4];
                a[mi][1] = Ab[(mb + g4 + 8) * SA + kk + t4];
                a[mi][2] = Ab[(mb + g4) * SA + kk + t4 + 4];
                a[mi][3] = Ab[(mb + g4 + 8) * SA + kk + t4 + 4];
            }
#pragma unroll
            for (int ni = 0; ni < 4; ni++) {
                int nb = wn + ni * 8 + g4;
                b[ni][0] = Bb[(kk + t4) * SB + nb];
                b[ni][1] = Bb[(kk + t4 + 4) * SB + nb];
            }
#pragma unroll
            for (int mi = 0; mi < 2; mi++)
#pragma unroll
                for (int ni = 0; ni < 4; ni++)
                    mma_tf32(c[mi][ni], a[mi][0], a[mi][1], a[mi][2], a[mi][3],
                             b[ni][0], b[ni][1]);
        }
        __syncthreads();   // compute(it) done before issue(it+2) overwrites buf
    }

    // ---- finalize LN stats ----
#pragma unroll
    for (int off = 4; off > 0; off >>= 1)
#pragma unroll
        for (int i = 0; i < 4; i++) {
            s1[i] += __shfl_xor_sync(0xffffffffu, s1[i], off);
            s2[i] += __shfl_xor_sync(0xffffffffu, s2[i], off);
        }
    if ((t & 7) == 0) {
#pragma unroll
        for (int i = 0; i < 4; i++) {
            float mu  = s1[i] * (1.f / FIN);
            float var = s2[i] * (1.f / FIN) - mu * mu;
            sstat[r0l + 32 * i] = make_float2(mu, rsqrtf(var + 1e-5f));
        }
    }
    if (is_attn && t < 128)
        *reinterpret_cast<float4*>(&slog[t][0]) = make_float4(0.f, 0.f, 0.f, 0.f);
    __syncthreads();

    float mu[4], rs[4];
    int   gi[4];
#pragma unroll
    for (int q = 0; q < 4; q++) {
        int rl = wm + g4 + 8 * q;
        float2 st = sstat[rl];
        mu[q] = st.x; rs[q] = st.y;
        gi[q] = bidx[m0 + rl];
    }

    if (!is_attn) {
#pragma unroll
        for (int mi = 0; mi < 2; mi++) {
#pragma unroll
            for (int ni = 0; ni < 4; ni++) {
                int n = n0 + wn + ni * 8 + 2 * t4;
                float2 u2  = *reinterpret_cast<const float2*>(&g_u[n]);
                float2 vb2 = *reinterpret_cast<const float2*>(&g_vb[n]);
#pragma unroll
                for (int hf = 0; hf < 2; hf++) {
                    int q = 2 * mi + hf;
                    float2 gg2 = *reinterpret_cast<const float2*>(&g_gg[gi[q] * NW + n]);
                    float o0 = rs[q] * (c[mi][ni][2 * hf]     - mu[q] * u2.x) + vb2.x + gg2.x;
                    float o1 = rs[q] * (c[mi][ni][2 * hf + 1] - mu[q] * u2.y) + vb2.y + gg2.y;
                    int rr = m0 + wm + mi * 16 + g4 + 8 * hf;
                    *reinterpret_cast<uint2*>(&g_h[(size_t)rr * H1D + n]) =
                        make_uint2(f2tf(silu_f(o0)), f2tf(silu_f(o1)));
                }
            }
        }
    } else {
        float pl[2][2][NH];
#pragma unroll
        for (int mi = 0; mi < 2; mi++)
#pragma unroll
            for (int hf = 0; hf < 2; hf++)
#pragma unroll
                for (int h = 0; h < NH; h++) pl[mi][hf][h] = 0.f;

#pragma unroll
        for (int mi = 0; mi < 2; mi++) {
#pragma unroll
            for (int ni = 0; ni < 4; ni++) {
                int nl = wn + ni * 8 + 2 * t4;
                int n  = H1D + nl;
                float2 u2  = *reinterpret_cast<const float2*>(&g_u[n]);
                float2 vb2 = *reinterpret_cast<const float2*>(&g_vb[n]);
                float4 a20 = *reinterpret_cast<const float4*>(&A2[nl * NH]);
                float4 a21 = *reinterpret_cast<const float4*>(&A2[(nl + 1) * NH]);
#pragma unroll
                for (int hf = 0; hf < 2; hf++) {
                    int q = 2 * mi + hf;
                    float2 gg2 = *reinterpret_cast<const float2*>(&g_gg[gi[q] * NW + n]);
                    float v0 = silu_f(rs[q] * (c[mi][ni][2 * hf]     - mu[q] * u2.x) + vb2.x + gg2.x);
                    float v1 = silu_f(rs[q] * (c[mi][ni][2 * hf + 1] - mu[q] * u2.y) + vb2.y + gg2.y);
                    pl[mi][hf][0] += v0 * a20.x + v1 * a21.x;
                    pl[mi][hf][1] += v0 * a20.y + v1 * a21.y;
                    pl[mi][hf][2] += v0 * a20.z + v1 * a21.z;
                    pl[mi][hf][3] += v0 * a20.w + v1 * a21.w;
                }
            }
        }
#pragma unroll
        for (int mi = 0; mi < 2; mi++)
#pragma unroll
            for (int hf = 0; hf < 2; hf++) {
                int rl = wm + mi * 16 + g4 + hf * 8;
#pragma unroll
                for (int h = 0; h < NH; h++)
                    atomicAdd(&slog[rl][h], pl[mi][hf][h]);
            }
        __syncthreads();

        if (t < 128) {
            int e = m0 + t;
            float4 l = *reinterpret_cast<float4*>(&slog[t][0]);
            float ae0 = __expf((l.x + ab2[0]) * 0.125f);
            float ae1 = __expf((l.y + ab2[1]) * 0.125f);
            float ae2 = __expf((l.z + ab2[2]) * 0.125f);
            float ae3 = __expf((l.w + ab2[3]) * 0.125f);
            *reinterpret_cast<float4*>(&g_ae[(size_t)e * NH]) = make_float4(ae0, ae1, ae2, ae3);
            int seg = bidx[e] * NNODE + ridx[e];
            atomicAdd(&g_den[seg * NH + 0], ae0);
            atomicAdd(&g_den[seg * NH + 1], ae1);
            atomicAdd(&g_den[seg * NH + 2], ae2);
            atomicAdd(&g_den[seg * NH + 3], ae3);
        }
    }
}

__global__ void invden_kernel()
{
    int i = blockIdx.x * blockDim.x + threadIdx.x;
    if (i < NSEG * NH) {
        float d = g_den[i];
        g_invden[i] = (d > 0.f) ? (1.f / d) : 0.f;
    }
}

// ================= GEMM2 + residual + pool, 2-stage cp.async, 3 CTAs/SM =================
__global__ void __launch_bounds__(256, 3) gemm2_fused(const float* __restrict__ b2,
                                                      const float* __restrict__ edges0,
                                                      const int* __restrict__ bidx,
                                                      const int* __restrict__ ridx,
                                                      float* __restrict__ Cout,
                                                      float* __restrict__ pooled)
{
    extern __shared__ uint32_t dyn[];
    uint32_t* As = dyn;
    uint32_t* Bs = dyn + NSTAGE * ASTRIDE;

    constexpr int LDA = H1D, NTOT = OUTD;
    const int t = threadIdx.x, lane = t & 31, wid = t >> 5;
    const int g4 = lane >> 2, t4 = lane & 3;
    const int wm = (wid & 3) * 32, wn = (wid >> 2) * 32;
    const int m0 = blockIdx.y * 128;

    float c[2][4][4];
#pragma unroll
    for (int mi = 0; mi < 2; mi++)
#pragma unroll
        for (int ni = 0; ni < 4; ni++)
#pragma unroll
            for (int q = 0; q < 4; q++) c[mi][ni][q] = 0.f;

    const uint32_t* Ap = g_h + (size_t)m0 * LDA;

    int arow[4], ac4[4];
#pragma unroll
    for (int i = 0; i < 4; i++) { int idx = t + 256 * i; arow[i] = idx >> 3; ac4[i] = idx & 7; }
    int brow[2], bc4[2];
#pragma unroll
    for (int i = 0; i < 2; i++) { int idx = t + 256 * i; brow[i] = idx >> 4; bc4[i] = idx & 15; }

    uint32_t aslot[4], bslot[2];
#pragma unroll
    for (int i = 0; i < 4; i++)
        aslot[i] = (uint32_t)__cvta_generic_to_shared(&As[arow[i] * SA + ac4[i] * 4]);
#pragma unroll
    for (int i = 0; i < 2; i++)
        bslot[i] = (uint32_t)__cvta_generic_to_shared(&Bs[brow[i] * SB + bc4[i] * 4]);

    auto issue = [&](int it) {
        int k0 = it * 32;
        uint32_t ab = (it & 1) * (ASTRIDE * 4);
        uint32_t bb = (it & 1) * (BSTRIDE * 4);
#pragma unroll
        for (int i = 0; i < 4; i++)
            CP16(aslot[i] + ab, Ap + (size_t)arow[i] * LDA + k0 + ac4[i] * 4);
#pragma unroll
        for (int i = 0; i < 2; i++)
            CP16(bslot[i] + bb, &g_W2tf[(size_t)(k0 + brow[i]) * NTOT + bc4[i] * 4]);
    };

    issue(0); CP_COMMIT();

    constexpr int NIT = H1D / 32;   // 8
#pragma unroll 1
    for (int it = 0; it < NIT; it++) {
        CP_WAIT0();
        __syncthreads();
        if (it + 1 < NIT) { issue(it + 1); CP_COMMIT(); }

        const int buf = it & 1;
        const uint32_t* Ab = As + buf * ASTRIDE;
        const uint32_t* Bb = Bs + buf * BSTRIDE;

#pragma unroll
        for (int ks = 0; ks < 4; ks++) {
            const int kk = ks * 8;
            uint32_t a[2][4], b[4][2];
#pragma unroll
            for (int mi = 0; mi < 2; mi++) {
                int mb = wm + mi * 16;
                a[mi][0] = Ab[(mb + g4) * SA + kk + t4];
                a[mi][1] = Ab[(mb + g4 + 8) * SA + kk + t4];
                a[mi][2] = Ab[(mb + g4) * SA + kk + t4 + 4];
                a[mi][3] = Ab[(mb + g4 + 8) * SA + kk + t4 + 4];
            }
#pragma unroll
            for (int ni = 0; ni < 4; ni++) {
                int nb = wn + ni * 8 + g4;
                b[ni][0] = Bb[(kk + t4) * SB + nb];
                b[ni][1] = Bb[(kk + t4 + 4) * SB + nb];
            }
#pragma unroll
            for (int mi = 0; mi < 2; mi++)
#pragma unroll
                for (int ni = 0; ni < 4; ni++)
                    mma_tf32(c[mi][ni], a[mi][0], a[mi][1], a[mi][2], a[mi][3],
                             b[ni][0], b[ni][1]);
        }
        __syncthreads();
    }

    int   segr[2][2];
    float aw[2][2][NH];
#pragma unroll
    for (int mi = 0; mi < 2; mi++)
#pragma unroll
        for (int hf = 0; hf < 2; hf++) {
            int r = m0 + wm + mi * 16 + g4 + hf * 8;
            int seg = bidx[r] * NNODE + ridx[r];
            segr[mi][hf] = seg;
            float4 ae4 = *reinterpret_cast<const float4*>(&g_ae[(size_t)r * NH]);
            float4 iv4 = *reinterpret_cast<const float4*>(&g_invden[(size_t)seg * NH]);
            aw[mi][hf][0] = ae4.x * iv4.x;
            aw[mi][hf][1] = ae4.y * iv4.y;
            aw[mi][hf][2] = ae4.z * iv4.z;
            aw[mi][hf][3] = ae4.w * iv4.w;
        }

#pragma unroll
    for (int mi = 0; mi < 2; mi++) {
#pragma unroll
        for (int ni = 0; ni < 4; ni++) {
            int n = wn + ni * 8 + 2 * t4;
            int h = n >> 4;
            float bv0 = b2[n], bv1 = b2[n + 1];
            int rr0 = m0 + wm + mi * 16 + g4;
            int rr1 = rr0 + 8;
            float2 e0 = *reinterpret_cast<const float2*>(&edges0[(size_t)rr0 * NTOT + n]);
            float2 e1 = *reinterpret_cast<const float2*>(&edges0[(size_t)rr1 * NTOT + n]);
            float o00 = c[mi][ni][0] + bv0 + e0.x;
            float o01 = c[mi][ni][1] + bv1 + e0.y;
            float o10 = c[mi][ni][2] + bv0 + e1.x;
            float o11 = c[mi][ni][3] + bv1 + e1.y;
            *reinterpret_cast<float2*>(&Cout[(size_t)rr0 * NTOT + n]) = make_float2(o00, o01);
            *reinterpret_cast<float2*>(&Cout[(size_t)rr1 * NTOT + n]) = make_float2(o10, o11);
            float w0 = aw[mi][0][h], w1 = aw[mi][1][h];
            atomicAdd(&pooled[(size_t)segr[mi][0] * OUTD + n],     o00 * w0);
            atomicAdd(&pooled[(size_t)segr[mi][0] * OUTD + n + 1], o01 * w0);
            atomicAdd(&pooled[(size_t)segr[mi][1] * OUTD + n],     o10 * w1);
            atomicAdd(&pooled[(size_t)segr[mi][1] * OUTD + n + 1], o11 * w1);
        }
    }
}

// ---------------- entry ----------------
extern "C" void kernel_launch(void* const* d_in, const int* in_sizes, int n_in,
                              void* d_out, int out_size)
{
    const float* nodes  = (const float*)d_in[0];
    const float* edges0 = (const float*)d_in[1];
    const float* globs  = (const float*)d_in[2];
    const float* ln_g   = (const float*)d_in[3];
    const float* ln_b   = (const float*)d_in[4];
    const float* W1     = (const float*)d_in[5];
    const float* b1     = (const float*)d_in[6];
    const float* W2     = (const float*)d_in[7];
    const float* b2     = (const float*)d_in[8];
    const float* A1     = (const float*)d_in[9];
    const float* ab1    = (const float*)d_in[10];
    const float* A2     = (const float*)d_in[11];
    const float* ab2    = (const float*)d_in[12];
    const int*   bidx   = (const int*)d_in[13];
    const int*   sidx   = (const int*)d_in[14];
    const int*   ridx   = (const int*)d_in[15];

    float* out    = (float*)d_out;
    float* newe   = out;
    float* pooled = out + (size_t)EDG * OUTD;

    static bool attr_done = false;
    if (!attr_done) {
        cudaFuncSetAttribute(gemm1_fused, cudaFuncAttributeMaxDynamicSharedMemorySize, DYN_SMEM);
        cudaFuncSetAttribute(gemm2_fused, cudaFuncAttributeMaxDynamicSharedMemorySize, DYN_SMEM);
        attr_done = true;
    }

    prep_kernel<<<(NSEG * OUTD + 255) / 256, 256>>>(W1, A1, W2, ln_g, pooled);
    prep2_kernel<<<1, NW>>>(W1, A1, b1, ab1, ln_g, ln_b, globs);
    gemm1_fused<<<dim3(5, EDG / 128), 256, DYN_SMEM>>>(nodes, edges0, bidx, sidx, ridx, A2, ab2);
    invden_kernel<<<(NSEG * NH + 255) / 256, 256>>>();
    gemm2_fused<<<dim3(1, EDG / 128), 256, DYN_SMEM>>>(b2, edges0, bidx, ridx, newe, pooled);
}